// round 11
// baseline (speedup 1.0000x reference)
#include <cuda_runtime.h>
#include <cstdint>
#include <math.h>
#include <mma.h>

using namespace nvcuda;

// ---------------- problem constants ----------------
#define DIMC   192
#define HW     56
#define WSZ    7
#define SHIFT  3
#define NHEADS 6
#define HD     32
#define HIDDEN 768
#define BATCH  32
#define NTOK   (HW*HW)          // 3136
#define NBLKS  (BATCH*64)       // 2048 windows
#define NTOKW  49

// ---------------- scratch ----------------
__device__ float g_xattn[(size_t)BATCH * NTOK * DIMC];

// ---------------- helpers ----------------
__device__ __forceinline__ float warp_sum(float v){
#pragma unroll
    for (int o = 16; o; o >>= 1) v += __shfl_xor_sync(0xffffffffu, v, o);
    return v;
}
__device__ __forceinline__ float warp_max(float v){
#pragma unroll
    for (int o = 16; o; o >>= 1) v = fmaxf(v, __shfl_xor_sync(0xffffffffu, v, o));
    return v;
}
__device__ __forceinline__ float gelu_exact(float x){
    return 0.5f * x * (1.0f + erff(x * 0.70710678118654752440f));
}
__device__ __forceinline__ float4 cvt4(float4 v){
    v.x = wmma::__float_to_tf32(v.x); v.y = wmma::__float_to_tf32(v.y);
    v.z = wmma::__float_to_tf32(v.z); v.w = wmma::__float_to_tf32(v.w);
    return v;
}

// cp.async helpers
__device__ __forceinline__ void cp_async16(void* smem, const void* gmem){
    unsigned int s = (unsigned int)__cvta_generic_to_shared(smem);
    asm volatile("cp.async.cg.shared.global [%0], [%1], 16;\n" :: "r"(s), "l"(gmem));
}
__device__ __forceinline__ void cp_commit(){
    asm volatile("cp.async.commit_group;\n");
}
template<int N>
__device__ __forceinline__ void cp_wait(){
    asm volatile("cp.async.wait_group %0;\n" :: "n"(N));
}

typedef wmma::fragment<wmma::matrix_a, 16, 16, 8, wmma::precision::tf32, wmma::row_major> FragA;
typedef wmma::fragment<wmma::matrix_b, 16, 16, 8, wmma::precision::tf32, wmma::row_major> FragB;
typedef wmma::fragment<wmma::matrix_b, 16, 16, 8, wmma::precision::tf32, wmma::col_major> FragBt;
typedef wmma::fragment<wmma::accumulator, 16, 16, 8, float> FragC;

// =====================================================================
// Kernel 1: shifted-window attention, one CTA per window, 16 warps.
// Conflict-free strides: A-operands %32==4 (196/68), B-operands %32==8
// (200). Register-prefetch weight stream (18 QKV + 6 proj chunks).
// =====================================================================
#define AT_THREADS 512
#define LD   196      // s_x / s_q / s_k
#define VLD  200      // s_v (B-operand)
#define SLD  68       // scores
#define BLD  200      // weight staging (B-operand)

#define OFF_Q  0
#define OFF_K  (64*LD)
#define OFF_V  (128*LD)
#define OFF_X  (OFF_V + 64*VLD)
#define OFF_B  (OFF_X + 64*LD)
#define ATT_SMEM_FLOATS (OFF_B + 32*BLD)     // 56832
#define ATT_SMEM_BYTES  (ATT_SMEM_FLOATS*4)  // 227328

__global__ __launch_bounds__(AT_THREADS)
void attn_kernel(const float* __restrict__ x,
                 const float* __restrict__ qkv_w, const float* __restrict__ qkv_b,
                 const float* __restrict__ proj_w, const float* __restrict__ proj_b,
                 const float* __restrict__ g1, const float* __restrict__ be1)
{
    extern __shared__ float sm[];
    float* s_q = sm + OFF_Q;     // Q -> later O
    float* s_k = sm + OFF_K;     // K -> later proj output
    float* s_v = sm + OFF_V;
    float* s_x = sm + OFF_X;     // gather/LN input; dead after QKV
    float* s_S = sm + OFF_X;     // 3-head scores [3][64][68]
    float* s_b = sm + OFF_B;     // weight staging [32][200]

    const int t   = threadIdx.x;
    const int wid = t >> 5, lane = t & 31;
    const int blk = blockIdx.x;
    const int b   = blk >> 6;
    const int win = blk & 63;
    const int wr  = win >> 3, wc = win & 7;

    const float* xb = x + (size_t)b * NTOK * DIMC;

    // per-thread staging coords: 1536 float4 / 512 threads = 3 each
    int prow[3], pc4[3];
#pragma unroll
    for (int i = 0; i < 3; i++){
        int idx = t + i*AT_THREADS;
        prow[i] = idx / 48; pc4[i] = idx - prow[i]*48;
    }
    float4 pf[3];

    // prefetch chunk 0 (m=0, kc=0 of qkv)
#pragma unroll
    for (int i = 0; i < 3; i++)
        pf[i] = *(const float4*)(qkv_w + (size_t)prow[i]*(3*DIMC) + pc4[i]*4);

    // zero pad rows 49..63 of s_x
    for (int idx = t; idx < 15*LD; idx += AT_THREADS) s_x[49*LD + idx] = 0.f;

    // gather with cyclic shift (roll -3,-3), float4
    for (int idx = t; idx < NTOKW*48; idx += AT_THREADS){
        int row = idx / 48, c4 = idx - row*48;
        int ti = row / WSZ, tj = row - ti*WSZ;
        int sr = wr*WSZ + ti + SHIFT; if (sr >= HW) sr -= HW;
        int sc = wc*WSZ + tj + SHIFT; if (sc >= HW) sc -= HW;
        *(float4*)(s_x + row*LD + c4*4) =
            *(const float4*)(xb + (size_t)(sr*HW + sc)*DIMC + c4*4);
    }
    __syncthreads();

    // LN1 in place (rows < 49), tf32 write
    for (int r = wid; r < NTOKW; r += 16){
        float s = 0.f, s2 = 0.f;
#pragma unroll
        for (int c = lane; c < DIMC; c += 32){
            float v = s_x[r*LD + c]; s += v; s2 += v*v;
        }
        s = warp_sum(s); s2 = warp_sum(s2);
        float mu = s * (1.0f/DIMC);
        float rs = rsqrtf(s2*(1.0f/DIMC) - mu*mu + 1e-5f);
#pragma unroll
        for (int c = lane; c < DIMC; c += 32){
            float v = (s_x[r*LD + c] - mu)*rs*g1[c] + be1[c];
            s_x[r*LD + c] = wmma::__float_to_tf32(v);
        }
    }

    // warp tiling for 64x192 GEMMs: 1 row tile x 3 col tiles per warp
    const int rt  = wid & 3;             // row tile 0..3
    const int cg3 = (wid >> 2) * 3;      // cols cg3, cg3+1, cg3+2

    int ci = 0;   // chunk stream position (0..23)

    // ---- QKV: 3 GEMMs [64,192]@[192,192] ----
    for (int m = 0; m < 3; m++){
        FragC acc[3];
#pragma unroll
        for (int j = 0; j < 3; j++) wmma::fill_fragment(acc[j], 0.f);

        for (int kc = 0; kc < 6; kc++){
            __syncthreads();   // previous chunk's mma readers of s_b done
#pragma unroll
            for (int i = 0; i < 3; i++)
                *(float4*)(s_b + prow[i]*BLD + pc4[i]*4) = cvt4(pf[i]);
            ci++;
            if (ci < 18){           // next qkv chunk
                int m2 = ci / 6, kc2 = ci - m2*6;
                const float* base = qkv_w + (size_t)(kc2*32)*(3*DIMC) + m2*DIMC;
#pragma unroll
                for (int i = 0; i < 3; i++)
                    pf[i] = *(const float4*)(base + (size_t)prow[i]*(3*DIMC) + pc4[i]*4);
            } else if (ci < 24){    // proj chunk
                int kc2 = ci - 18;
                const float* base = proj_w + (size_t)(kc2*32)*DIMC;
#pragma unroll
                for (int i = 0; i < 3; i++)
                    pf[i] = *(const float4*)(base + (size_t)prow[i]*DIMC + pc4[i]*4);
            }
            __syncthreads();
#pragma unroll
            for (int ks = 0; ks < 4; ks++){
                FragA fa;
                wmma::load_matrix_sync(fa, s_x + rt*16*LD + kc*32 + ks*8, LD);
#pragma unroll
                for (int j = 0; j < 3; j++){
                    FragB fb;
                    wmma::load_matrix_sync(fb, s_b + ks*8*BLD + (cg3+j)*16, BLD);
                    wmma::mma_sync(acc[j], fa, fb, acc[j]);
                }
            }
        }
        float* dst = (m == 0) ? s_q : (m == 1) ? s_k : s_v;
        const int dstld = (m == 2) ? VLD : LD;
#pragma unroll
        for (int j = 0; j < 3; j++)
            wmma::store_matrix_sync(dst + rt*16*dstld + (cg3+j)*16, acc[j], dstld,
                                    wmma::mem_row_major);
    }
    __syncthreads();

    // bias + tf32 round q,k,v (pad rows already exact 0)
    for (int idx = t; idx < NTOKW*DIMC; idx += AT_THREADS){
        int r = idx / DIMC, c = idx - r*DIMC;
        s_q[r*LD  + c] = wmma::__float_to_tf32(s_q[r*LD  + c] + qkv_b[c]);
        s_k[r*LD  + c] = wmma::__float_to_tf32(s_k[r*LD  + c] + qkv_b[DIMC + c]);
        s_v[r*VLD + c] = wmma::__float_to_tf32(s_v[r*VLD + c] + qkv_b[2*DIMC + c]);
    }
    __syncthreads();   // QKV reads of s_x done -> s_S may overwrite

    // ---- head groups of 3 ----
    for (int g = 0; g < 2; g++){
        // S = scale * Q K^T for 3 heads: 48 tiles, 3 per warp
#pragma unroll
        for (int i = 0; i < 3; i++){
            int tt = wid + 16*i;
            int hh = tt >> 4, rem = tt & 15;
            int ti = rem >> 2, tj = rem & 3;
            int h = 3*g + hh;
            FragC sacc; wmma::fill_fragment(sacc, 0.f);
#pragma unroll
            for (int ks = 0; ks < 4; ks++){
                FragA fa;  wmma::load_matrix_sync(fa, s_q + h*HD + ti*16*LD + ks*8, LD);
                FragBt fb; wmma::load_matrix_sync(fb, s_k + h*HD + tj*16*LD + ks*8, LD);
                wmma::mma_sync(sacc, fa, fb, sacc);
            }
#pragma unroll
            for (int e = 0; e < sacc.num_elements; e++)
                sacc.x[e] *= 0.17677669529663688110f;
            wmma::store_matrix_sync(s_S + hh*64*SLD + ti*16*SLD + tj*16, sacc, SLD,
                                    wmma::mem_row_major);
        }
        __syncthreads();

        // softmax: 3*49 rows, fp32 math, tf32 write
        for (int rr = wid; rr < 3*NTOKW; rr += 16){
            int hh = rr / NTOKW, r = rr - hh*NTOKW;
            float* row = s_S + hh*64*SLD + r*SLD;
            float v0 = (lane      < NTOKW) ? row[lane     ] : -1e30f;
            float v1 = (lane + 32 < NTOKW) ? row[lane + 32] : -1e30f;
            float m  = warp_max(fmaxf(v0, v1));
            float e0 = (lane      < NTOKW) ? __expf(v0 - m) : 0.f;
            float e1 = (lane + 32 < NTOKW) ? __expf(v1 - m) : 0.f;
            float inv = 1.0f / warp_sum(e0 + e1);
            if (lane      < NTOKW) row[lane     ] = wmma::__float_to_tf32(e0 * inv);
            if (lane + 32 < NTOKW) row[lane + 32] = wmma::__float_to_tf32(e1 * inv);
        }
        __syncthreads();

        // PV: O_h[64,32] = P[64,64] @ V_h[64,32]; 24 tiles over 16 warps.
#pragma unroll
        for (int i = 0; i < 2; i++){
            int tt = wid + 16*i;
            if (tt < 24){
                int hh = tt >> 3, rem = tt & 7;
                int ti = rem >> 1, tj = rem & 1;
                int h = 3*g + hh;
                FragC oacc; wmma::fill_fragment(oacc, 0.f);
#pragma unroll
                for (int ks = 0; ks < 8; ks++){
                    FragA fa; wmma::load_matrix_sync(fa, s_S + hh*64*SLD + ti*16*SLD + ks*8, SLD);
                    FragB fb; wmma::load_matrix_sync(fb, s_v + h*HD + ks*8*VLD + tj*16, VLD);
                    wmma::mma_sync(oacc, fa, fb, oacc);
                }
#pragma unroll
                for (int e = 0; e < oacc.num_elements; e++)
                    oacc.x[e] = wmma::__float_to_tf32(oacc.x[e]);
                wmma::store_matrix_sync(s_q + h*HD + ti*16*LD + tj*16, oacc, LD,
                                        wmma::mem_row_major);
            }
        }
        __syncthreads();
    }

    // ---- proj: [64,192]@[192,192]; A = s_q (O, tf32, pad rows 0) ----
    {
        FragC acc[3];
#pragma unroll
        for (int j = 0; j < 3; j++) wmma::fill_fragment(acc[j], 0.f);

        for (int kc = 0; kc < 6; kc++){
            __syncthreads();   // PV reads of s_S (overlaps s_b) / prev mma done
#pragma unroll
            for (int i = 0; i < 3; i++)
                *(float4*)(s_b + prow[i]*BLD + pc4[i]*4) = cvt4(pf[i]);
            ci++;
            if (ci < 24){
                int kc2 = ci - 18;
                const float* base = proj_w + (size_t)(kc2*32)*DIMC;
#pragma unroll
                for (int i = 0; i < 3; i++)
                    pf[i] = *(const float4*)(base + (size_t)prow[i]*DIMC + pc4[i]*4);
            }
            __syncthreads();
#pragma unroll
            for (int ks = 0; ks < 4; ks++){
                FragA fa;
                wmma::load_matrix_sync(fa, s_q + rt*16*LD + kc*32 + ks*8, LD);
#pragma unroll
                for (int j = 0; j < 3; j++){
                    FragB fb;
                    wmma::load_matrix_sync(fb, s_b + ks*8*BLD + (cg3+j)*16, BLD);
                    wmma::mma_sync(acc[j], fa, fb, acc[j]);
                }
            }
        }
#pragma unroll
        for (int j = 0; j < 3; j++)
            wmma::store_matrix_sync(s_k + rt*16*LD + (cg3+j)*16, acc[j], LD,
                                    wmma::mem_row_major);
        __syncthreads();

        // scatter (roll +3,+3) + proj bias
        float* ob = g_xattn + (size_t)b * NTOK * DIMC;
        for (int idx = t; idx < NTOKW*48; idx += AT_THREADS){
            int row = idx / 48, c4 = idx - row*48;
            int ti2 = row / WSZ, tj2 = row - ti2*WSZ;
            int sr = wr*WSZ + ti2 + SHIFT; if (sr >= HW) sr -= HW;
            int sc = wc*WSZ + tj2 + SHIFT; if (sc >= HW) sc -= HW;
            float4 v  = *(float4*)(s_k + row*LD + c4*4);
            float4 pb = *(const float4*)(proj_b + c4*4);
            v.x += pb.x; v.y += pb.y; v.z += pb.z; v.w += pb.w;
            *(float4*)(ob + (size_t)(sr*HW + sc)*DIMC + c4*4) = v;
        }
    }
}

// =====================================================================
// Kernel 2: fused MLP, 2 CTAs/SM. TM=64 tokens/CTA, 256 threads,
// single-buffered weights (smem 110KB), 24 chunks of 32 hidden.
// =====================================================================
#define ML_THREADS 256
#define TM 64
#define TH 32
#define XLD  196
#define W1LD 36     // ≡4 mod 32: 2-way conflict on B loads, accepted for occupancy
#define HLD  36
#define W2LD 200
#define MO_XN 0
#define MO_W1 (MO_XN + TM*XLD)        // 12544
#define MO_H  (MO_W1 + 192*W1LD)      // 19456
#define MO_W2 (MO_H  + TM*HLD)        // 21760
#define MLP_SMEM_FLOATS (MO_W2 + 32*W2LD)   // 28160
#define MLP_SMEM_BYTES  (MLP_SMEM_FLOATS*4) // 112640 (2 CTAs/SM)

__global__ __launch_bounds__(ML_THREADS, 2)
void mlp_kernel(const float* __restrict__ g2, const float* __restrict__ be2,
                const float* __restrict__ w1, const float* __restrict__ b1,
                const float* __restrict__ w2, const float* __restrict__ b2,
                float* __restrict__ out)
{
    extern __shared__ float sm[];
    float* s_xn = sm + MO_XN;   // [64][196]
    float* s_w1 = sm + MO_W1;   // [192][36]
    float* s_h  = sm + MO_H;    // [64][36]
    float* s_w2 = sm + MO_W2;   // [32][200]

    const int t = threadIdx.x;
    const int wid = t >> 5, lane = t & 31;
    const size_t tok0 = (size_t)blockIdx.x * TM;
    const float* xb = g_xattn + tok0 * DIMC;

    for (int idx = t; idx < TM*48; idx += ML_THREADS){
        int r = idx / 48, c4 = idx - r*48;
        *(float4*)(s_xn + r*XLD + c4*4) = *(const float4*)(xb + (size_t)r*DIMC + c4*4);
    }
    __syncthreads();

    // LN2, tf32 write
    for (int r = wid; r < TM; r += 8){
        float s = 0.f, s2 = 0.f;
#pragma unroll
        for (int c = lane; c < DIMC; c += 32){
            float v = s_xn[r*XLD + c]; s += v; s2 += v*v;
        }
        s = warp_sum(s); s2 = warp_sum(s2);
        float mu = s * (1.0f/DIMC);
        float rs = rsqrtf(s2*(1.0f/DIMC) - mu*mu + 1e-5f);
#pragma unroll
        for (int c = lane; c < DIMC; c += 32){
            float v = (s_xn[r*XLD + c] - mu)*rs*g2[c] + be2[c];
            s_xn[r*XLD + c] = wmma::__float_to_tf32(v);
        }
    }

    const int r1 = wid & 3, c1 = wid >> 2;     // GEMM1: 4x2 grid, 1 tile/warp
    const int rp = wid & 1, cp = wid >> 1;     // GEMM2: 2x3 tiles/warp (2x4 warp grid)

    FragC acc2[2][3];
#pragma unroll
    for (int i = 0; i < 2; i++)
#pragma unroll
        for (int j = 0; j < 3; j++) wmma::fill_fragment(acc2[i][j], 0.f);

    for (int hc = 0; hc < 24; hc++){
        const int h0 = hc * TH;
        __syncthreads();   // prev GEMM1/GEMM2 done reading w1/w2/s_h (iter0: LN order)

        // stage w1 [192][32] + w2 [32][192] via cp.async (6+6 float4/thread)
#pragma unroll
        for (int i = 0; i < 6; i++){
            int id = t + i*ML_THREADS;
            int row = id >> 3, c4 = id & 7;
            cp_async16(s_w1 + row*W1LD + c4*4, w1 + (size_t)row*HIDDEN + h0 + c4*4);
        }
#pragma unroll
        for (int i = 0; i < 6; i++){
            int id = t + i*ML_THREADS;
            int row = id / 48, c4 = id - row*48;
            cp_async16(s_w2 + row*W2LD + c4*4, w2 + (size_t)(h0 + row)*DIMC + c4*4);
        }
        cp_commit();
        cp_wait<0>();
        // RN-round exactly what this thread copied
#pragma unroll
        for (int i = 0; i < 6; i++){
            int id = t + i*ML_THREADS;
            int row = id >> 3, c4 = id & 7;
            float4* p = (float4*)(s_w1 + row*W1LD + c4*4); *p = cvt4(*p);
        }
#pragma unroll
        for (int i = 0; i < 6; i++){
            int id = t + i*ML_THREADS;
            int row = id / 48, c4 = id - row*48;
            float4* p = (float4*)(s_w2 + row*W2LD + c4*4); *p = cvt4(*p);
        }
        __syncthreads();   // staged + rounded weights visible

        // GEMM1: H[64,32] = Xn[64,192] @ W1c[192,32]; 2 interleaved chains
        FragC a1e, a1o;
        wmma::fill_fragment(a1e, 0.f);
        wmma::fill_fragment(a1o, 0.f);
#pragma unroll
        for (int ks = 0; ks < 12; ks++){
            FragA fae, fao; FragB fbe, fbo;
            wmma::load_matrix_sync(fae, s_xn + r1*16*XLD + (2*ks  )*8, XLD);
            wmma::load_matrix_sync(fbe, s_w1 + (2*ks  )*8*W1LD + c1*16, W1LD);
            wmma::load_matrix_sync(fao, s_xn + r1*16*XLD + (2*ks+1)*8, XLD);
            wmma::load_matrix_sync(fbo, s_w1 + (2*ks+1)*8*W1LD + c1*16, W1LD);
            wmma::mma_sync(a1e, fae, fbe, a1e);
            wmma::mma_sync(a1o, fao, fbo, a1o);
        }
#pragma unroll
        for (int e = 0; e < a1e.num_elements; e++) a1e.x[e] += a1o.x[e];
        wmma::store_matrix_sync(s_h + r1*16*HLD + c1*16, a1e, HLD, wmma::mem_row_major);
        __syncwarp();
        {   // bias + exact GELU on own tile, tf32 write
            float* tb = s_h + r1*16*HLD + c1*16;
            const float* bp = b1 + h0 + c1*16;
#pragma unroll
            for (int e = lane; e < 256; e += 32){
                int rr2 = e >> 4, cc = e & 15;
                float v = tb[rr2*HLD + cc] + bp[cc];
                tb[rr2*HLD + cc] = wmma::__float_to_tf32(gelu_exact(v));
            }
        }
        __syncthreads();   // s_h fully visible

        // GEMM2: acc2 += H[64,32] @ W2c[32,192]; 2x3 tiles/warp
#pragma unroll
        for (int ks = 0; ks < 4; ks++){
            FragA fa0, fa1;
            wmma::load_matrix_sync(fa0, s_h + (2*rp  )*16*HLD + ks*8, HLD);
            wmma::load_matrix_sync(fa1, s_h + (2*rp+1)*16*HLD + ks*8, HLD);
#pragma unroll
            for (int j = 0; j < 3; j++){
                FragB fb; wmma::load_matrix_sync(fb, s_w2 + ks*8*W2LD + (3*cp + j)*16, W2LD);
                wmma::mma_sync(acc2[0][j], fa0, fb, acc2[0][j]);
                wmma::mma_sync(acc2[1][j], fa1, fb, acc2[1][j]);
            }
        }
    }
    __syncthreads();   // last GEMM1 readers of s_xn done

    // epilogue: acc2 -> s_xn (overwrite), then residual + bias, coalesced out
#pragma unroll
    for (int i = 0; i < 2; i++)
#pragma unroll
        for (int j = 0; j < 3; j++)
            wmma::store_matrix_sync(s_xn + (2*rp+i)*16*XLD + (3*cp+j)*16, acc2[i][j],
                                    XLD, wmma::mem_row_major);
    __syncthreads();

    float* ob = out + tok0 * DIMC;
    for (int idx = t; idx < TM*48; idx += ML_THREADS){
        int r = idx / 48, c4 = idx - r*48;
        float4 a  = *(float4*)(s_xn + r*XLD + c4*4);
        float4 xr = *(const float4*)(xb + (size_t)r*DIMC + c4*4);
        float4 bb = *(const float4*)(b2 + c4*4);
        a.x += xr.x + bb.x; a.y += xr.y + bb.y;
        a.z += xr.z + bb.z; a.w += xr.w + bb.w;
        *(float4*)(ob + (size_t)r*DIMC + c4*4) = a;
    }
}

// =====================================================================
// launch
// =====================================================================
extern "C" void kernel_launch(void* const* d_in, const int* in_sizes, int n_in,
                              void* d_out, int out_size)
{
    (void)in_sizes; (void)n_in; (void)out_size;
    const float* x      = (const float*)d_in[0];
    const float* qkv_w  = (const float*)d_in[1];
    const float* qkv_b  = (const float*)d_in[2];
    const float* proj_w = (const float*)d_in[3];
    const float* proj_b = (const float*)d_in[4];
    const float* g1     = (const float*)d_in[5];
    const float* be1    = (const float*)d_in[6];
    const float* g2     = (const float*)d_in[7];
    const float* be2    = (const float*)d_in[8];
    const float* w1     = (const float*)d_in[9];
    const float* b1     = (const float*)d_in[10];
    const float* w2     = (const float*)d_in[11];
    const float* b2     = (const float*)d_in[12];
    float* out = (float*)d_out;

    cudaFuncSetAttribute(attn_kernel, cudaFuncAttributeMaxDynamicSharedMemorySize, ATT_SMEM_BYTES);
    cudaFuncSetAttribute(mlp_kernel,  cudaFuncAttributeMaxDynamicSharedMemorySize, MLP_SMEM_BYTES);

    attn_kernel<<<NBLKS, AT_THREADS, ATT_SMEM_BYTES>>>(x, qkv_w, qkv_b, proj_w, proj_b, g1, be1);
    mlp_kernel<<<(BATCH*NTOK)/TM, ML_THREADS, MLP_SMEM_BYTES>>>(g2, be2, w1, b1, w2, b2, out);
}

// round 12
// speedup vs baseline: 1.1162x; 1.1162x over previous
#include <cuda_runtime.h>
#include <cstdint>
#include <math.h>
#include <mma.h>

using namespace nvcuda;

// ---------------- problem constants ----------------
#define DIMC   192
#define HW     56
#define WSZ    7
#define SHIFT  3
#define NHEADS 6
#define HD     32
#define HIDDEN 768
#define BATCH  32
#define NTOK   (HW*HW)          // 3136
#define NBLKS  (BATCH*64)       // 2048 windows
#define NTOKW  49

// ---------------- scratch ----------------
__device__ float g_xattn[(size_t)BATCH * NTOK * DIMC];

// ---------------- helpers ----------------
__device__ __forceinline__ float warp_sum(float v){
#pragma unroll
    for (int o = 16; o; o >>= 1) v += __shfl_xor_sync(0xffffffffu, v, o);
    return v;
}
__device__ __forceinline__ float warp_max(float v){
#pragma unroll
    for (int o = 16; o; o >>= 1) v = fmaxf(v, __shfl_xor_sync(0xffffffffu, v, o));
    return v;
}
__device__ __forceinline__ float gelu_exact(float x){
    return 0.5f * x * (1.0f + erff(x * 0.70710678118654752440f));
}
__device__ __forceinline__ float4 cvt4(float4 v){
    v.x = wmma::__float_to_tf32(v.x); v.y = wmma::__float_to_tf32(v.y);
    v.z = wmma::__float_to_tf32(v.z); v.w = wmma::__float_to_tf32(v.w);
    return v;
}

// cp.async helpers
__device__ __forceinline__ void cp_async16(void* smem, const void* gmem){
    unsigned int s = (unsigned int)__cvta_generic_to_shared(smem);
    asm volatile("cp.async.cg.shared.global [%0], [%1], 16;\n" :: "r"(s), "l"(gmem));
}
__device__ __forceinline__ void cp_commit(){
    asm volatile("cp.async.commit_group;\n");
}
template<int N>
__device__ __forceinline__ void cp_wait(){
    asm volatile("cp.async.wait_group %0;\n" :: "n"(N));
}

typedef wmma::fragment<wmma::matrix_a, 16, 16, 8, wmma::precision::tf32, wmma::row_major> FragA;
typedef wmma::fragment<wmma::matrix_b, 16, 16, 8, wmma::precision::tf32, wmma::row_major> FragB;
typedef wmma::fragment<wmma::matrix_b, 16, 16, 8, wmma::precision::tf32, wmma::col_major> FragBt;
typedef wmma::fragment<wmma::accumulator, 16, 16, 8, float> FragC;

// =====================================================================
// Kernel 1 (R10-proven): shifted-window attention, one CTA per window,
// 384 threads, 2x2 warp tiles, register-prefetch weight stream.
// Conflict-free strides: A-operands %32==4 (196/68), B-operands %32==8 (200).
// =====================================================================
#define AT_THREADS 384
#define LD   196      // s_x / s_q / s_k
#define VLD  200      // s_v (B-operand)
#define SLD  68       // scores
#define BLD  200      // weight staging (B-operand)

#define OFF_Q  0
#define OFF_K  (64*LD)
#define OFF_V  (128*LD)
#define OFF_X  (OFF_V + 64*VLD)
#define OFF_B  (OFF_X + 64*LD)
#define ATT_SMEM_FLOATS (OFF_B + 32*BLD)     // 56832
#define ATT_SMEM_BYTES  (ATT_SMEM_FLOATS*4)  // 227328

__global__ __launch_bounds__(AT_THREADS)
void attn_kernel(const float* __restrict__ x,
                 const float* __restrict__ qkv_w, const float* __restrict__ qkv_b,
                 const float* __restrict__ proj_w, const float* __restrict__ proj_b,
                 const float* __restrict__ g1, const float* __restrict__ be1)
{
    extern __shared__ float sm[];
    float* s_q = sm + OFF_Q;     // Q -> later O
    float* s_k = sm + OFF_K;     // K -> later proj output
    float* s_v = sm + OFF_V;
    float* s_x = sm + OFF_X;     // gather/LN input; dead after QKV
    float* s_S = sm + OFF_X;     // 3-head scores [3][64][68]
    float* s_b = sm + OFF_B;     // weight staging [32][200]

    const int t   = threadIdx.x;
    const int wid = t >> 5, lane = t & 31;
    const int blk = blockIdx.x;
    const int b   = blk >> 6;
    const int win = blk & 63;
    const int wr  = win >> 3, wc = win & 7;

    const float* xb = x + (size_t)b * NTOK * DIMC;

    // per-thread staging coords: 1536 float4 per chunk / 384 threads = 4 each
    int prow[4], pc4[4];
#pragma unroll
    for (int i = 0; i < 4; i++){
        int idx = t + i*AT_THREADS;
        prow[i] = idx / 48; pc4[i] = idx - prow[i]*48;
    }
    float4 pf[4];

    // prefetch chunk 0 (m=0, kc=0 of qkv)
#pragma unroll
    for (int i = 0; i < 4; i++)
        pf[i] = *(const float4*)(qkv_w + (size_t)prow[i]*(3*DIMC) + pc4[i]*4);

    // zero pad rows 49..63 of s_x
    for (int idx = t; idx < 15*LD; idx += AT_THREADS) s_x[49*LD + idx] = 0.f;

    // gather with cyclic shift (roll -3,-3), float4
    for (int idx = t; idx < NTOKW*48; idx += AT_THREADS){
        int row = idx / 48, c4 = idx - row*48;
        int ti = row / WSZ, tj = row - ti*WSZ;
        int sr = wr*WSZ + ti + SHIFT; if (sr >= HW) sr -= HW;
        int sc = wc*WSZ + tj + SHIFT; if (sc >= HW) sc -= HW;
        *(float4*)(s_x + row*LD + c4*4) =
            *(const float4*)(xb + (size_t)(sr*HW + sc)*DIMC + c4*4);
    }
    __syncthreads();

    // LN1 in place (rows < 49), tf32 write
    for (int r = wid; r < NTOKW; r += 12){
        float s = 0.f, s2 = 0.f;
#pragma unroll
        for (int c = lane; c < DIMC; c += 32){
            float v = s_x[r*LD + c]; s += v; s2 += v*v;
        }
        s = warp_sum(s); s2 = warp_sum(s2);
        float mu = s * (1.0f/DIMC);
        float rs = rsqrtf(s2*(1.0f/DIMC) - mu*mu + 1e-5f);
#pragma unroll
        for (int c = lane; c < DIMC; c += 32){
            float v = (s_x[r*LD + c] - mu)*rs*g1[c] + be1[c];
            s_x[r*LD + c] = wmma::__float_to_tf32(v);
        }
    }

    // warp tiling for 64x192 GEMMs: 2 row-tiles x 2 col-tiles per warp
    const int rt0 = (wid / 6) * 2;   // row tiles rt0, rt0+1
    const int cgi = wid % 6;         // col tiles cgi, cgi+6

    int ci = 0;   // chunk stream position (0..23)

    // ---- QKV: 3 GEMMs [64,192]@[192,192] ----
    for (int m = 0; m < 3; m++){
        FragC acc[2][2];
#pragma unroll
        for (int i = 0; i < 2; i++)
#pragma unroll
            for (int j = 0; j < 2; j++) wmma::fill_fragment(acc[i][j], 0.f);

        for (int kc = 0; kc < 6; kc++){
            __syncthreads();   // previous chunk's mma readers of s_b done
#pragma unroll
            for (int i = 0; i < 4; i++)
                *(float4*)(s_b + prow[i]*BLD + pc4[i]*4) = cvt4(pf[i]);
            ci++;
            if (ci < 18){           // next qkv chunk
                int m2 = ci / 6, kc2 = ci - m2*6;
                const float* base = qkv_w + (size_t)(kc2*32)*(3*DIMC) + m2*DIMC;
#pragma unroll
                for (int i = 0; i < 4; i++)
                    pf[i] = *(const float4*)(base + (size_t)prow[i]*(3*DIMC) + pc4[i]*4);
            } else if (ci < 24){    // proj chunk
                int kc2 = ci - 18;
                const float* base = proj_w + (size_t)(kc2*32)*DIMC;
#pragma unroll
                for (int i = 0; i < 4; i++)
                    pf[i] = *(const float4*)(base + (size_t)prow[i]*DIMC + pc4[i]*4);
            }
            __syncthreads();
#pragma unroll
            for (int ks = 0; ks < 4; ks++){
                FragA fa0, fa1;
                wmma::load_matrix_sync(fa0, s_x + (rt0  )*16*LD + kc*32 + ks*8, LD);
                wmma::load_matrix_sync(fa1, s_x + (rt0+1)*16*LD + kc*32 + ks*8, LD);
                FragB fb0, fb1;
                wmma::load_matrix_sync(fb0, s_b + ks*8*BLD + cgi*16, BLD);
                wmma::load_matrix_sync(fb1, s_b + ks*8*BLD + (cgi+6)*16, BLD);
                wmma::mma_sync(acc[0][0], fa0, fb0, acc[0][0]);
                wmma::mma_sync(acc[0][1], fa0, fb1, acc[0][1]);
                wmma::mma_sync(acc[1][0], fa1, fb0, acc[1][0]);
                wmma::mma_sync(acc[1][1], fa1, fb1, acc[1][1]);
            }
        }
        float* dst = (m == 0) ? s_q : (m == 1) ? s_k : s_v;
        const int dstld = (m == 2) ? VLD : LD;
#pragma unroll
        for (int i = 0; i < 2; i++){
            wmma::store_matrix_sync(dst + (rt0+i)*16*dstld + cgi*16,     acc[i][0], dstld, wmma::mem_row_major);
            wmma::store_matrix_sync(dst + (rt0+i)*16*dstld + (cgi+6)*16, acc[i][1], dstld, wmma::mem_row_major);
        }
    }
    __syncthreads();

    // bias + tf32 round q,k,v (pad rows already exact 0)
    for (int idx = t; idx < NTOKW*DIMC; idx += AT_THREADS){
        int r = idx / DIMC, c = idx - r*DIMC;
        s_q[r*LD  + c] = wmma::__float_to_tf32(s_q[r*LD  + c] + qkv_b[c]);
        s_k[r*LD  + c] = wmma::__float_to_tf32(s_k[r*LD  + c] + qkv_b[DIMC + c]);
        s_v[r*VLD + c] = wmma::__float_to_tf32(s_v[r*VLD + c] + qkv_b[2*DIMC + c]);
    }
    __syncthreads();   // QKV phase reads of s_x done -> s_S may overwrite

    // ---- head groups of 3 ----
    for (int g = 0; g < 2; g++){
        // S = scale * Q K^T for 3 heads: 48 tiles, 4 per warp
#pragma unroll
        for (int i = 0; i < 4; i++){
            int tt = wid + 12*i;
            int hh = tt >> 4, rem = tt & 15;
            int ti = rem >> 2, tj = rem & 3;
            int h = 3*g + hh;
            FragC sacc; wmma::fill_fragment(sacc, 0.f);
#pragma unroll
            for (int ks = 0; ks < 4; ks++){
                FragA fa;  wmma::load_matrix_sync(fa, s_q + h*HD + ti*16*LD + ks*8, LD);
                FragBt fb; wmma::load_matrix_sync(fb, s_k + h*HD + tj*16*LD + ks*8, LD);
                wmma::mma_sync(sacc, fa, fb, sacc);
            }
#pragma unroll
            for (int e = 0; e < sacc.num_elements; e++)
                sacc.x[e] *= 0.17677669529663688110f;
            wmma::store_matrix_sync(s_S + hh*64*SLD + ti*16*SLD + tj*16, sacc, SLD,
                                    wmma::mem_row_major);
        }
        __syncthreads();

        // softmax: 3*49 rows, fp32 math, tf32 write (cols>=49 stay exact 0)
        for (int rr = wid; rr < 3*NTOKW; rr += 12){
            int hh = rr / NTOKW, r = rr - hh*NTOKW;
            float* row = s_S + hh*64*SLD + r*SLD;
            float v0 = (lane      < NTOKW) ? row[lane     ] : -1e30f;
            float v1 = (lane + 32 < NTOKW) ? row[lane + 32] : -1e30f;
            float m  = warp_max(fmaxf(v0, v1));
            float e0 = (lane      < NTOKW) ? __expf(v0 - m) : 0.f;
            float e1 = (lane + 32 < NTOKW) ? __expf(v1 - m) : 0.f;
            float inv = 1.0f / warp_sum(e0 + e1);
            if (lane      < NTOKW) row[lane     ] = wmma::__float_to_tf32(e0 * inv);
            if (lane + 32 < NTOKW) row[lane + 32] = wmma::__float_to_tf32(e1 * inv);
        }
        __syncthreads();

        // PV: O_h[64,32] = P[64,64] @ V_h[64,32]; 24 tiles, 2 per warp.
#pragma unroll
        for (int i = 0; i < 2; i++){
            int tt = wid + 12*i;
            int hh = tt >> 3, rem = tt & 7;
            int ti = rem >> 1, tj = rem & 1;
            int h = 3*g + hh;
            FragC oacc; wmma::fill_fragment(oacc, 0.f);
#pragma unroll
            for (int ks = 0; ks < 8; ks++){
                FragA fa; wmma::load_matrix_sync(fa, s_S + hh*64*SLD + ti*16*SLD + ks*8, SLD);
                FragB fb; wmma::load_matrix_sync(fb, s_v + h*HD + ks*8*VLD + tj*16, VLD);
                wmma::mma_sync(oacc, fa, fb, oacc);
            }
#pragma unroll
            for (int e = 0; e < oacc.num_elements; e++)
                oacc.x[e] = wmma::__float_to_tf32(oacc.x[e]);
            wmma::store_matrix_sync(s_q + h*HD + ti*16*LD + tj*16, oacc, LD,
                                    wmma::mem_row_major);
        }
        __syncthreads();
    }

    // ---- proj: [64,192]@[192,192]; A = s_q (O, tf32, pad rows 0) ----
    {
        FragC acc[2][2];
#pragma unroll
        for (int i = 0; i < 2; i++)
#pragma unroll
            for (int j = 0; j < 2; j++) wmma::fill_fragment(acc[i][j], 0.f);

        for (int kc = 0; kc < 6; kc++){
            __syncthreads();   // PV reads of s_S (overlaps s_b) / prev mma done
#pragma unroll
            for (int i = 0; i < 4; i++)
                *(float4*)(s_b + prow[i]*BLD + pc4[i]*4) = cvt4(pf[i]);
            ci++;
            if (ci < 24){
                int kc2 = ci - 18;
                const float* base = proj_w + (size_t)(kc2*32)*DIMC;
#pragma unroll
                for (int i = 0; i < 4; i++)
                    pf[i] = *(const float4*)(base + (size_t)prow[i]*DIMC + pc4[i]*4);
            }
            __syncthreads();
#pragma unroll
            for (int ks = 0; ks < 4; ks++){
                FragA fa0, fa1;
                wmma::load_matrix_sync(fa0, s_q + (rt0  )*16*LD + kc*32 + ks*8, LD);
                wmma::load_matrix_sync(fa1, s_q + (rt0+1)*16*LD + kc*32 + ks*8, LD);
                FragB fb0, fb1;
                wmma::load_matrix_sync(fb0, s_b + ks*8*BLD + cgi*16, BLD);
                wmma::load_matrix_sync(fb1, s_b + ks*8*BLD + (cgi+6)*16, BLD);
                wmma::mma_sync(acc[0][0], fa0, fb0, acc[0][0]);
                wmma::mma_sync(acc[0][1], fa0, fb1, acc[0][1]);
                wmma::mma_sync(acc[1][0], fa1, fb0, acc[1][0]);
                wmma::mma_sync(acc[1][1], fa1, fb1, acc[1][1]);
            }
        }
#pragma unroll
        for (int i = 0; i < 2; i++){
            wmma::store_matrix_sync(s_k + (rt0+i)*16*LD + cgi*16,     acc[i][0], LD, wmma::mem_row_major);
            wmma::store_matrix_sync(s_k + (rt0+i)*16*LD + (cgi+6)*16, acc[i][1], LD, wmma::mem_row_major);
        }
        __syncthreads();

        // scatter (roll +3,+3) + proj bias
        float* ob = g_xattn + (size_t)b * NTOK * DIMC;
        for (int idx = t; idx < NTOKW*48; idx += AT_THREADS){
            int row = idx / 48, c4 = idx - row*48;
            int ti2 = row / WSZ, tj2 = row - ti2*WSZ;
            int sr = wr*WSZ + ti2 + SHIFT; if (sr >= HW) sr -= HW;
            int sc = wc*WSZ + tj2 + SHIFT; if (sc >= HW) sc -= HW;
            float4 v  = *(float4*)(s_k + row*LD + c4*4);
            float4 pb = *(const float4*)(proj_b + c4*4);
            v.x += pb.x; v.y += pb.y; v.z += pb.z; v.w += pb.w;
            *(float4*)(ob + (size_t)(sr*HW + sc)*DIMC + c4*4) = v;
        }
    }
}

// =====================================================================
// Kernel 2 (R11-proven): fused MLP, 2 CTAs/SM. TM=64 tokens/CTA,
// 256 threads, single-buffered weights (smem 110KB), 24 chunks of 32.
// =====================================================================
#define ML_THREADS 256
#define TM 64
#define TH 32
#define XLD  196
#define W1LD 36     // ≡4 mod 32: 2-way conflict on B loads, accepted for occupancy
#define HLD  36
#define W2LD 200
#define MO_XN 0
#define MO_W1 (MO_XN + TM*XLD)        // 12544
#define MO_H  (MO_W1 + 192*W1LD)      // 19456
#define MO_W2 (MO_H  + TM*HLD)        // 21760
#define MLP_SMEM_FLOATS (MO_W2 + 32*W2LD)   // 28160
#define MLP_SMEM_BYTES  (MLP_SMEM_FLOATS*4) // 112640 (2 CTAs/SM)

__global__ __launch_bounds__(ML_THREADS, 2)
void mlp_kernel(const float* __restrict__ g2, const float* __restrict__ be2,
                const float* __restrict__ w1, const float* __restrict__ b1,
                const float* __restrict__ w2, const float* __restrict__ b2,
                float* __restrict__ out)
{
    extern __shared__ float sm[];
    float* s_xn = sm + MO_XN;   // [64][196]
    float* s_w1 = sm + MO_W1;   // [192][36]
    float* s_h  = sm + MO_H;    // [64][36]
    float* s_w2 = sm + MO_W2;   // [32][200]

    const int t = threadIdx.x;
    const int wid = t >> 5, lane = t & 31;
    const size_t tok0 = (size_t)blockIdx.x * TM;
    const float* xb = g_xattn + tok0 * DIMC;

    for (int idx = t; idx < TM*48; idx += ML_THREADS){
        int r = idx / 48, c4 = idx - r*48;
        *(float4*)(s_xn + r*XLD + c4*4) = *(const float4*)(xb + (size_t)r*DIMC + c4*4);
    }
    __syncthreads();

    // LN2, tf32 write
    for (int r = wid; r < TM; r += 8){
        float s = 0.f, s2 = 0.f;
#pragma unroll
        for (int c = lane; c < DIMC; c += 32){
            float v = s_xn[r*XLD + c]; s += v; s2 += v*v;
        }
        s = warp_sum(s); s2 = warp_sum(s2);
        float mu = s * (1.0f/DIMC);
        float rs = rsqrtf(s2*(1.0f/DIMC) - mu*mu + 1e-5f);
#pragma unroll
        for (int c = lane; c < DIMC; c += 32){
            float v = (s_xn[r*XLD + c] - mu)*rs*g2[c] + be2[c];
            s_xn[r*XLD + c] = wmma::__float_to_tf32(v);
        }
    }

    const int r1 = wid & 3, c1 = wid >> 2;     // GEMM1: 4x2 grid, 1 tile/warp
    const int rp = wid & 1, cp = wid >> 1;     // GEMM2: 2x3 tiles/warp (2x4 warp grid)

    FragC acc2[2][3];
#pragma unroll
    for (int i = 0; i < 2; i++)
#pragma unroll
        for (int j = 0; j < 3; j++) wmma::fill_fragment(acc2[i][j], 0.f);

    for (int hc = 0; hc < 24; hc++){
        const int h0 = hc * TH;
        __syncthreads();   // prev GEMM1/GEMM2 done reading w1/w2/s_h (iter0: LN order)

        // stage w1 [192][32] + w2 [32][192] via cp.async (6+6 float4/thread)
#pragma unroll
        for (int i = 0; i < 6; i++){
            int id = t + i*ML_THREADS;
            int row = id >> 3, c4 = id & 7;
            cp_async16(s_w1 + row*W1LD + c4*4, w1 + (size_t)row*HIDDEN + h0 + c4*4);
        }
#pragma unroll
        for (int i = 0; i < 6; i++){
            int id = t + i*ML_THREADS;
            int row = id / 48, c4 = id - row*48;
            cp_async16(s_w2 + row*W2LD + c4*4, w2 + (size_t)(h0 + row)*DIMC + c4*4);
        }
        cp_commit();
        cp_wait<0>();
        // RN-round exactly what this thread copied
#pragma unroll
        for (int i = 0; i < 6; i++){
            int id = t + i*ML_THREADS;
            int row = id >> 3, c4 = id & 7;
            float4* p = (float4*)(s_w1 + row*W1LD + c4*4); *p = cvt4(*p);
        }
#pragma unroll
        for (int i = 0; i < 6; i++){
            int id = t + i*ML_THREADS;
            int row = id / 48, c4 = id - row*48;
            float4* p = (float4*)(s_w2 + row*W2LD + c4*4); *p = cvt4(*p);
        }
        __syncthreads();   // staged + rounded weights visible

        // GEMM1: H[64,32] = Xn[64,192] @ W1c[192,32]; 2 interleaved chains
        FragC a1e, a1o;
        wmma::fill_fragment(a1e, 0.f);
        wmma::fill_fragment(a1o, 0.f);
#pragma unroll
        for (int ks = 0; ks < 12; ks++){
            FragA fae, fao; FragB fbe, fbo;
            wmma::load_matrix_sync(fae, s_xn + r1*16*XLD + (2*ks  )*8, XLD);
            wmma::load_matrix_sync(fbe, s_w1 + (2*ks  )*8*W1LD + c1*16, W1LD);
            wmma::load_matrix_sync(fao, s_xn + r1*16*XLD + (2*ks+1)*8, XLD);
            wmma::load_matrix_sync(fbo, s_w1 + (2*ks+1)*8*W1LD + c1*16, W1LD);
            wmma::mma_sync(a1e, fae, fbe, a1e);
            wmma::mma_sync(a1o, fao, fbo, a1o);
        }
#pragma unroll
        for (int e = 0; e < a1e.num_elements; e++) a1e.x[e] += a1o.x[e];
        wmma::store_matrix_sync(s_h + r1*16*HLD + c1*16, a1e, HLD, wmma::mem_row_major);
        __syncwarp();
        {   // bias + exact GELU on own tile, tf32 write
            float* tb = s_h + r1*16*HLD + c1*16;
            const float* bp = b1 + h0 + c1*16;
#pragma unroll
            for (int e = lane; e < 256; e += 32){
                int rr2 = e >> 4, cc = e & 15;
                float v = tb[rr2*HLD + cc] + bp[cc];
                tb[rr2*HLD + cc] = wmma::__float_to_tf32(gelu_exact(v));
            }
        }
        __syncthreads();   // s_h fully visible

        // GEMM2: acc2 += H[64,32] @ W2c[32,192]; 2x3 tiles/warp
#pragma unroll
        for (int ks = 0; ks < 4; ks++){
            FragA fa0, fa1;
            wmma::load_matrix_sync(fa0, s_h + (2*rp  )*16*HLD + ks*8, HLD);
            wmma::load_matrix_sync(fa1, s_h + (2*rp+1)*16*HLD + ks*8, HLD);
#pragma unroll
            for (int j = 0; j < 3; j++){
                FragB fb; wmma::load_matrix_sync(fb, s_w2 + ks*8*W2LD + (3*cp + j)*16, W2LD);
                wmma::mma_sync(acc2[0][j], fa0, fb, acc2[0][j]);
                wmma::mma_sync(acc2[1][j], fa1, fb, acc2[1][j]);
            }
        }
    }
    __syncthreads();   // last GEMM1 readers of s_xn done

    // epilogue: acc2 -> s_xn (overwrite), then residual + bias, coalesced out
#pragma unroll
    for (int i = 0; i < 2; i++)
#pragma unroll
        for (int j = 0; j < 3; j++)
            wmma::store_matrix_sync(s_xn + (2*rp+i)*16*XLD + (3*cp+j)*16, acc2[i][j],
                                    XLD, wmma::mem_row_major);
    __syncthreads();

    float* ob = out + tok0 * DIMC;
    for (int idx = t; idx < TM*48; idx += ML_THREADS){
        int r = idx / 48, c4 = idx - r*48;
        float4 a  = *(float4*)(s_xn + r*XLD + c4*4);
        float4 xr = *(const float4*)(xb + (size_t)r*DIMC + c4*4);
        float4 bb = *(const float4*)(b2 + c4*4);
        a.x += xr.x + bb.x; a.y += xr.y + bb.y;
        a.z += xr.z + bb.z; a.w += xr.w + bb.w;
        *(float4*)(ob + (size_t)r*DIMC + c4*4) = a;
    }
}

// =====================================================================
// launch
// =====================================================================
extern "C" void kernel_launch(void* const* d_in, const int* in_sizes, int n_in,
                              void* d_out, int out_size)
{
    (void)in_sizes; (void)n_in; (void)out_size;
    const float* x      = (const float*)d_in[0];
    const float* qkv_w  = (const float*)d_in[1];
    const float* qkv_b  = (const float*)d_in[2];
    const float* proj_w = (const float*)d_in[3];
    const float* proj_b = (const float*)d_in[4];
    const float* g1     = (const float*)d_in[5];
    const float* be1    = (const float*)d_in[6];
    const float* g2     = (const float*)d_in[7];
    const float* be2    = (const float*)d_in[8];
    const float* w1     = (const float*)d_in[9];
    const float* b1     = (const float*)d_in[10];
    const float* w2     = (const float*)d_in[11];
    const float* b2     = (const float*)d_in[12];
    float* out = (float*)d_out;

    cudaFuncSetAttribute(attn_kernel, cudaFuncAttributeMaxDynamicSharedMemorySize, ATT_SMEM_BYTES);
    cudaFuncSetAttribute(mlp_kernel,  cudaFuncAttributeMaxDynamicSharedMemorySize, MLP_SMEM_BYTES);

    attn_kernel<<<NBLKS, AT_THREADS, ATT_SMEM_BYTES>>>(x, qkv_w, qkv_b, proj_w, proj_b, g1, be1);
    mlp_kernel<<<(BATCH*NTOK)/TM, ML_THREADS, MLP_SMEM_BYTES>>>(g2, be2, w1, b1, w2, b2, out);
}

// round 13
// speedup vs baseline: 1.1665x; 1.0451x over previous
#include <cuda_runtime.h>
#include <cstdint>
#include <math.h>
#include <mma.h>

using namespace nvcuda;

// ---------------- problem constants ----------------
#define DIMC   192
#define HW     56
#define WSZ    7
#define SHIFT  3
#define NHEADS 6
#define HD     32
#define HIDDEN 768
#define BATCH  32
#define NTOK   (HW*HW)          // 3136
#define NBLKS  (BATCH*64)       // 2048 windows
#define NTOKW  49

// ---------------- scratch ----------------
__device__ float g_xattn[(size_t)BATCH * NTOK * DIMC];

// tf32-pre-rounded weight copies (filled once per launch by round_weights_kernel)
#define NW1   (DIMC*HIDDEN)     // 147456
#define NW2   (HIDDEN*DIMC)     // 147456
#define NQKV  (DIMC*3*DIMC)     // 110592
#define NPROJ (DIMC*DIMC)       // 36864
__device__ float g_w1r[NW1];
__device__ float g_w2r[NW2];
__device__ float g_qkvr[NQKV];
__device__ float g_projr[NPROJ];

// ---------------- helpers ----------------
__device__ __forceinline__ float warp_sum(float v){
#pragma unroll
    for (int o = 16; o; o >>= 1) v += __shfl_xor_sync(0xffffffffu, v, o);
    return v;
}
__device__ __forceinline__ float warp_max(float v){
#pragma unroll
    for (int o = 16; o; o >>= 1) v = fmaxf(v, __shfl_xor_sync(0xffffffffu, v, o));
    return v;
}
__device__ __forceinline__ float gelu_exact(float x){
    return 0.5f * x * (1.0f + erff(x * 0.70710678118654752440f));
}
__device__ __forceinline__ float4 cvt4(float4 v){
    v.x = wmma::__float_to_tf32(v.x); v.y = wmma::__float_to_tf32(v.y);
    v.z = wmma::__float_to_tf32(v.z); v.w = wmma::__float_to_tf32(v.w);
    return v;
}

// cp.async helpers
__device__ __forceinline__ void cp_async16(void* smem, const void* gmem){
    unsigned int s = (unsigned int)__cvta_generic_to_shared(smem);
    asm volatile("cp.async.cg.shared.global [%0], [%1], 16;\n" :: "r"(s), "l"(gmem));
}
__device__ __forceinline__ void cp_commit(){
    asm volatile("cp.async.commit_group;\n");
}
template<int N>
__device__ __forceinline__ void cp_wait(){
    asm volatile("cp.async.wait_group %0;\n" :: "n"(N));
}

typedef wmma::fragment<wmma::matrix_a, 16, 16, 8, wmma::precision::tf32, wmma::row_major> FragA;
typedef wmma::fragment<wmma::matrix_b, 16, 16, 8, wmma::precision::tf32, wmma::row_major> FragB;
typedef wmma::fragment<wmma::matrix_b, 16, 16, 8, wmma::precision::tf32, wmma::col_major> FragBt;
typedef wmma::fragment<wmma::accumulator, 16, 16, 8, float> FragC;

// =====================================================================
// Kernel 0: RN-round all weights to tf32 once (110592 float4 total).
// =====================================================================
#define RW_THREADS 256
#define RW_BLOCKS  432   // 110592 / 256

__global__ __launch_bounds__(RW_THREADS)
void round_weights_kernel(const float* __restrict__ w1, const float* __restrict__ w2,
                          const float* __restrict__ qkv_w, const float* __restrict__ proj_w)
{
    int i = blockIdx.x * RW_THREADS + threadIdx.x;    // float4 index
    if (i < NW1/4){
        ((float4*)g_w1r)[i] = cvt4(((const float4*)w1)[i]); return;
    }
    i -= NW1/4;
    if (i < NW2/4){
        ((float4*)g_w2r)[i] = cvt4(((const float4*)w2)[i]); return;
    }
    i -= NW2/4;
    if (i < NQKV/4){
        ((float4*)g_qkvr)[i] = cvt4(((const float4*)qkv_w)[i]); return;
    }
    i -= NQKV/4;
    if (i < NPROJ/4){
        ((float4*)g_projr)[i] = cvt4(((const float4*)proj_w)[i]);
    }
}

// =====================================================================
// Kernel 1 (R10-proven structure): shifted-window attention, one CTA per
// window, 384 threads, 2x2 warp tiles, register-prefetch weight stream.
// Weights come pre-rounded from g_qkvr/g_projr (no cvt in staging).
// =====================================================================
#define AT_THREADS 384
#define LD   196      // s_x / s_q / s_k
#define VLD  200      // s_v (B-operand)
#define SLD  68       // scores
#define BLD  200      // weight staging (B-operand)

#define OFF_Q  0
#define OFF_K  (64*LD)
#define OFF_V  (128*LD)
#define OFF_X  (OFF_V + 64*VLD)
#define OFF_B  (OFF_X + 64*LD)
#define ATT_SMEM_FLOATS (OFF_B + 32*BLD)     // 56832
#define ATT_SMEM_BYTES  (ATT_SMEM_FLOATS*4)  // 227328

__global__ __launch_bounds__(AT_THREADS)
void attn_kernel(const float* __restrict__ x,
                 const float* __restrict__ qkv_b,
                 const float* __restrict__ proj_b,
                 const float* __restrict__ g1, const float* __restrict__ be1)
{
    extern __shared__ float sm[];
    float* s_q = sm + OFF_Q;     // Q -> later O
    float* s_k = sm + OFF_K;     // K -> later proj output
    float* s_v = sm + OFF_V;
    float* s_x = sm + OFF_X;     // gather/LN input; dead after QKV
    float* s_S = sm + OFF_X;     // 3-head scores [3][64][68]
    float* s_b = sm + OFF_B;     // weight staging [32][200]

    const int t   = threadIdx.x;
    const int wid = t >> 5, lane = t & 31;
    const int blk = blockIdx.x;
    const int b   = blk >> 6;
    const int win = blk & 63;
    const int wr  = win >> 3, wc = win & 7;

    const float* xb = x + (size_t)b * NTOK * DIMC;

    // per-thread staging coords: 1536 float4 per chunk / 384 threads = 4 each
    int prow[4], pc4[4];
#pragma unroll
    for (int i = 0; i < 4; i++){
        int idx = t + i*AT_THREADS;
        prow[i] = idx / 48; pc4[i] = idx - prow[i]*48;
    }
    float4 pf[4];

    // prefetch chunk 0 (m=0, kc=0 of qkv) from pre-rounded weights
#pragma unroll
    for (int i = 0; i < 4; i++)
        pf[i] = *(const float4*)(g_qkvr + (size_t)prow[i]*(3*DIMC) + pc4[i]*4);

    // zero pad rows 49..63 of s_x
    for (int idx = t; idx < 15*LD; idx += AT_THREADS) s_x[49*LD + idx] = 0.f;

    // gather with cyclic shift (roll -3,-3), float4
    for (int idx = t; idx < NTOKW*48; idx += AT_THREADS){
        int row = idx / 48, c4 = idx - row*48;
        int ti = row / WSZ, tj = row - ti*WSZ;
        int sr = wr*WSZ + ti + SHIFT; if (sr >= HW) sr -= HW;
        int sc = wc*WSZ + tj + SHIFT; if (sc >= HW) sc -= HW;
        *(float4*)(s_x + row*LD + c4*4) =
            *(const float4*)(xb + (size_t)(sr*HW + sc)*DIMC + c4*4);
    }
    __syncthreads();

    // LN1 in place (rows < 49), tf32 write
    for (int r = wid; r < NTOKW; r += 12){
        float s = 0.f, s2 = 0.f;
#pragma unroll
        for (int c = lane; c < DIMC; c += 32){
            float v = s_x[r*LD + c]; s += v; s2 += v*v;
        }
        s = warp_sum(s); s2 = warp_sum(s2);
        float mu = s * (1.0f/DIMC);
        float rs = rsqrtf(s2*(1.0f/DIMC) - mu*mu + 1e-5f);
#pragma unroll
        for (int c = lane; c < DIMC; c += 32){
            float v = (s_x[r*LD + c] - mu)*rs*g1[c] + be1[c];
            s_x[r*LD + c] = wmma::__float_to_tf32(v);
        }
    }

    // warp tiling for 64x192 GEMMs: 2 row-tiles x 2 col-tiles per warp
    const int rt0 = (wid / 6) * 2;   // row tiles rt0, rt0+1
    const int cgi = wid % 6;         // col tiles cgi, cgi+6

    int ci = 0;   // chunk stream position (0..23)

    // ---- QKV: 3 GEMMs [64,192]@[192,192] ----
    for (int m = 0; m < 3; m++){
        FragC acc[2][2];
#pragma unroll
        for (int i = 0; i < 2; i++)
#pragma unroll
            for (int j = 0; j < 2; j++) wmma::fill_fragment(acc[i][j], 0.f);

        for (int kc = 0; kc < 6; kc++){
            __syncthreads();   // previous chunk's mma readers of s_b done
#pragma unroll
            for (int i = 0; i < 4; i++)
                *(float4*)(s_b + prow[i]*BLD + pc4[i]*4) = pf[i];
            ci++;
            if (ci < 18){           // next qkv chunk
                int m2 = ci / 6, kc2 = ci - m2*6;
                const float* base = g_qkvr + (size_t)(kc2*32)*(3*DIMC) + m2*DIMC;
#pragma unroll
                for (int i = 0; i < 4; i++)
                    pf[i] = *(const float4*)(base + (size_t)prow[i]*(3*DIMC) + pc4[i]*4);
            } else if (ci < 24){    // proj chunk
                int kc2 = ci - 18;
                const float* base = g_projr + (size_t)(kc2*32)*DIMC;
#pragma unroll
                for (int i = 0; i < 4; i++)
                    pf[i] = *(const float4*)(base + (size_t)prow[i]*DIMC + pc4[i]*4);
            }
            __syncthreads();
#pragma unroll
            for (int ks = 0; ks < 4; ks++){
                FragA fa0, fa1;
                wmma::load_matrix_sync(fa0, s_x + (rt0  )*16*LD + kc*32 + ks*8, LD);
                wmma::load_matrix_sync(fa1, s_x + (rt0+1)*16*LD + kc*32 + ks*8, LD);
                FragB fb0, fb1;
                wmma::load_matrix_sync(fb0, s_b + ks*8*BLD + cgi*16, BLD);
                wmma::load_matrix_sync(fb1, s_b + ks*8*BLD + (cgi+6)*16, BLD);
                wmma::mma_sync(acc[0][0], fa0, fb0, acc[0][0]);
                wmma::mma_sync(acc[0][1], fa0, fb1, acc[0][1]);
                wmma::mma_sync(acc[1][0], fa1, fb0, acc[1][0]);
                wmma::mma_sync(acc[1][1], fa1, fb1, acc[1][1]);
            }
        }
        float* dst = (m == 0) ? s_q : (m == 1) ? s_k : s_v;
        const int dstld = (m == 2) ? VLD : LD;
#pragma unroll
        for (int i = 0; i < 2; i++){
            wmma::store_matrix_sync(dst + (rt0+i)*16*dstld + cgi*16,     acc[i][0], dstld, wmma::mem_row_major);
            wmma::store_matrix_sync(dst + (rt0+i)*16*dstld + (cgi+6)*16, acc[i][1], dstld, wmma::mem_row_major);
        }
    }
    __syncthreads();

    // bias + tf32 round q,k,v (pad rows already exact 0)
    for (int idx = t; idx < NTOKW*DIMC; idx += AT_THREADS){
        int r = idx / DIMC, c = idx - r*DIMC;
        s_q[r*LD  + c] = wmma::__float_to_tf32(s_q[r*LD  + c] + qkv_b[c]);
        s_k[r*LD  + c] = wmma::__float_to_tf32(s_k[r*LD  + c] + qkv_b[DIMC + c]);
        s_v[r*VLD + c] = wmma::__float_to_tf32(s_v[r*VLD + c] + qkv_b[2*DIMC + c]);
    }
    __syncthreads();   // QKV phase reads of s_x done -> s_S may overwrite

    // ---- head groups of 3 ----
    for (int g = 0; g < 2; g++){
        // S = scale * Q K^T for 3 heads: 48 tiles, 4 per warp
#pragma unroll
        for (int i = 0; i < 4; i++){
            int tt = wid + 12*i;
            int hh = tt >> 4, rem = tt & 15;
            int ti = rem >> 2, tj = rem & 3;
            int h = 3*g + hh;
            FragC sacc; wmma::fill_fragment(sacc, 0.f);
#pragma unroll
            for (int ks = 0; ks < 4; ks++){
                FragA fa;  wmma::load_matrix_sync(fa, s_q + h*HD + ti*16*LD + ks*8, LD);
                FragBt fb; wmma::load_matrix_sync(fb, s_k + h*HD + tj*16*LD + ks*8, LD);
                wmma::mma_sync(sacc, fa, fb, sacc);
            }
#pragma unroll
            for (int e = 0; e < sacc.num_elements; e++)
                sacc.x[e] *= 0.17677669529663688110f;
            wmma::store_matrix_sync(s_S + hh*64*SLD + ti*16*SLD + tj*16, sacc, SLD,
                                    wmma::mem_row_major);
        }
        __syncthreads();

        // softmax: 3*49 rows, fp32 math, tf32 write (cols>=49 stay exact 0)
        for (int rr = wid; rr < 3*NTOKW; rr += 12){
            int hh = rr / NTOKW, r = rr - hh*NTOKW;
            float* row = s_S + hh*64*SLD + r*SLD;
            float v0 = (lane      < NTOKW) ? row[lane     ] : -1e30f;
            float v1 = (lane + 32 < NTOKW) ? row[lane + 32] : -1e30f;
            float m  = warp_max(fmaxf(v0, v1));
            float e0 = (lane      < NTOKW) ? __expf(v0 - m) : 0.f;
            float e1 = (lane + 32 < NTOKW) ? __expf(v1 - m) : 0.f;
            float inv = 1.0f / warp_sum(e0 + e1);
            if (lane      < NTOKW) row[lane     ] = wmma::__float_to_tf32(e0 * inv);
            if (lane + 32 < NTOKW) row[lane + 32] = wmma::__float_to_tf32(e1 * inv);
        }
        __syncthreads();

        // PV: O_h[64,32] = P[64,64] @ V_h[64,32]; 24 tiles, 2 per warp.
#pragma unroll
        for (int i = 0; i < 2; i++){
            int tt = wid + 12*i;
            int hh = tt >> 3, rem = tt & 7;
            int ti = rem >> 1, tj = rem & 1;
            int h = 3*g + hh;
            FragC oacc; wmma::fill_fragment(oacc, 0.f);
#pragma unroll
            for (int ks = 0; ks < 8; ks++){
                FragA fa; wmma::load_matrix_sync(fa, s_S + hh*64*SLD + ti*16*SLD + ks*8, SLD);
                FragB fb; wmma::load_matrix_sync(fb, s_v + h*HD + ks*8*VLD + tj*16, VLD);
                wmma::mma_sync(oacc, fa, fb, oacc);
            }
#pragma unroll
            for (int e = 0; e < oacc.num_elements; e++)
                oacc.x[e] = wmma::__float_to_tf32(oacc.x[e]);
            wmma::store_matrix_sync(s_q + h*HD + ti*16*LD + tj*16, oacc, LD,
                                    wmma::mem_row_major);
        }
        __syncthreads();
    }

    // ---- proj: [64,192]@[192,192]; A = s_q (O, tf32, pad rows 0) ----
    {
        FragC acc[2][2];
#pragma unroll
        for (int i = 0; i < 2; i++)
#pragma unroll
            for (int j = 0; j < 2; j++) wmma::fill_fragment(acc[i][j], 0.f);

        for (int kc = 0; kc < 6; kc++){
            __syncthreads();   // PV reads of s_S (overlaps s_b) / prev mma done
#pragma unroll
            for (int i = 0; i < 4; i++)
                *(float4*)(s_b + prow[i]*BLD + pc4[i]*4) = pf[i];
            ci++;
            if (ci < 24){
                int kc2 = ci - 18;
                const float* base = g_projr + (size_t)(kc2*32)*DIMC;
#pragma unroll
                for (int i = 0; i < 4; i++)
                    pf[i] = *(const float4*)(base + (size_t)prow[i]*DIMC + pc4[i]*4);
            }
            __syncthreads();
#pragma unroll
            for (int ks = 0; ks < 4; ks++){
                FragA fa0, fa1;
                wmma::load_matrix_sync(fa0, s_q + (rt0  )*16*LD + kc*32 + ks*8, LD);
                wmma::load_matrix_sync(fa1, s_q + (rt0+1)*16*LD + kc*32 + ks*8, LD);
                FragB fb0, fb1;
                wmma::load_matrix_sync(fb0, s_b + ks*8*BLD + cgi*16, BLD);
                wmma::load_matrix_sync(fb1, s_b + ks*8*BLD + (cgi+6)*16, BLD);
                wmma::mma_sync(acc[0][0], fa0, fb0, acc[0][0]);
                wmma::mma_sync(acc[0][1], fa0, fb1, acc[0][1]);
                wmma::mma_sync(acc[1][0], fa1, fb0, acc[1][0]);
                wmma::mma_sync(acc[1][1], fa1, fb1, acc[1][1]);
            }
        }
#pragma unroll
        for (int i = 0; i < 2; i++){
            wmma::store_matrix_sync(s_k + (rt0+i)*16*LD + cgi*16,     acc[i][0], LD, wmma::mem_row_major);
            wmma::store_matrix_sync(s_k + (rt0+i)*16*LD + (cgi+6)*16, acc[i][1], LD, wmma::mem_row_major);
        }
        __syncthreads();

        // scatter (roll +3,+3) + proj bias
        float* ob = g_xattn + (size_t)b * NTOK * DIMC;
        for (int idx = t; idx < NTOKW*48; idx += AT_THREADS){
            int row = idx / 48, c4 = idx - row*48;
            int ti2 = row / WSZ, tj2 = row - ti2*WSZ;
            int sr = wr*WSZ + ti2 + SHIFT; if (sr >= HW) sr -= HW;
            int sc = wc*WSZ + tj2 + SHIFT; if (sc >= HW) sc -= HW;
            float4 v  = *(float4*)(s_k + row*LD + c4*4);
            float4 pb = *(const float4*)(proj_b + c4*4);
            v.x += pb.x; v.y += pb.y; v.z += pb.z; v.w += pb.w;
            *(float4*)(ob + (size_t)(sr*HW + sc)*DIMC + c4*4) = v;
        }
    }
}

// =====================================================================
// Kernel 2: fused MLP, 2 CTAs/SM, TM=64/256 threads. Weights arrive
// pre-rounded (no RMW pass); w1 and w2 in separate commit groups so
// w2's latency hides behind GEMM1 + GELU.
// =====================================================================
#define ML_THREADS 256
#define TM 64
#define TH 32
#define XLD  196
#define W1LD 36
#define HLD  36
#define W2LD 200
#define MO_XN 0
#define MO_W1 (MO_XN + TM*XLD)        // 12544
#define MO_H  (MO_W1 + 192*W1LD)      // 19456
#define MO_W2 (MO_H  + TM*HLD)        // 21760
#define MLP_SMEM_FLOATS (MO_W2 + 32*W2LD)   // 28160
#define MLP_SMEM_BYTES  (MLP_SMEM_FLOATS*4) // 112640 (2 CTAs/SM)

__global__ __launch_bounds__(ML_THREADS, 2)
void mlp_kernel(const float* __restrict__ g2, const float* __restrict__ be2,
                const float* __restrict__ b1, const float* __restrict__ b2,
                float* __restrict__ out)
{
    extern __shared__ float sm[];
    float* s_xn = sm + MO_XN;   // [64][196]
    float* s_w1 = sm + MO_W1;   // [192][36]
    float* s_h  = sm + MO_H;    // [64][36]
    float* s_w2 = sm + MO_W2;   // [32][200]

    const int t = threadIdx.x;
    const int wid = t >> 5, lane = t & 31;
    const size_t tok0 = (size_t)blockIdx.x * TM;
    const float* xb = g_xattn + tok0 * DIMC;

    for (int idx = t; idx < TM*48; idx += ML_THREADS){
        int r = idx / 48, c4 = idx - r*48;
        *(float4*)(s_xn + r*XLD + c4*4) = *(const float4*)(xb + (size_t)r*DIMC + c4*4);
    }
    __syncthreads();

    // LN2, tf32 write
    for (int r = wid; r < TM; r += 8){
        float s = 0.f, s2 = 0.f;
#pragma unroll
        for (int c = lane; c < DIMC; c += 32){
            float v = s_xn[r*XLD + c]; s += v; s2 += v*v;
        }
        s = warp_sum(s); s2 = warp_sum(s2);
        float mu = s * (1.0f/DIMC);
        float rs = rsqrtf(s2*(1.0f/DIMC) - mu*mu + 1e-5f);
#pragma unroll
        for (int c = lane; c < DIMC; c += 32){
            float v = (s_xn[r*XLD + c] - mu)*rs*g2[c] + be2[c];
            s_xn[r*XLD + c] = wmma::__float_to_tf32(v);
        }
    }

    const int r1 = wid & 3, c1 = wid >> 2;     // GEMM1: 4x2 grid, 1 tile/warp
    const int rp = wid & 1, cp = wid >> 1;     // GEMM2: 2x3 tiles/warp (2x4 warp grid)

    FragC acc2[2][3];
#pragma unroll
    for (int i = 0; i < 2; i++)
#pragma unroll
        for (int j = 0; j < 3; j++) wmma::fill_fragment(acc2[i][j], 0.f);

    for (int hc = 0; hc < 24; hc++){
        const int h0 = hc * TH;
        __syncthreads();   // prev GEMM1/GEMM2 done reading w1/w2/s_h (iter0: LN order)

        // stage w1 [192][32] (group 1)
#pragma unroll
        for (int i = 0; i < 6; i++){
            int id = t + i*ML_THREADS;
            int row = id >> 3, c4 = id & 7;
            cp_async16(s_w1 + row*W1LD + c4*4, g_w1r + (size_t)row*HIDDEN + h0 + c4*4);
        }
        cp_commit();
        // stage w2 [32][192] (group 2)
#pragma unroll
        for (int i = 0; i < 6; i++){
            int id = t + i*ML_THREADS;
            int row = id / 48, c4 = id - row*48;
            cp_async16(s_w2 + row*W2LD + c4*4, g_w2r + (size_t)(h0 + row)*DIMC + c4*4);
        }
        cp_commit();

        cp_wait<1>();      // w1 arrived (w2 still in flight)
        __syncthreads();   // w1 visible CTA-wide

        // GEMM1: H[64,32] = Xn[64,192] @ W1c[192,32]; 2 interleaved chains
        FragC a1e, a1o;
        wmma::fill_fragment(a1e, 0.f);
        wmma::fill_fragment(a1o, 0.f);
#pragma unroll
        for (int ks = 0; ks < 12; ks++){
            FragA fae, fao; FragB fbe, fbo;
            wmma::load_matrix_sync(fae, s_xn + r1*16*XLD + (2*ks  )*8, XLD);
            wmma::load_matrix_sync(fbe, s_w1 + (2*ks  )*8*W1LD + c1*16, W1LD);
            wmma::load_matrix_sync(fao, s_xn + r1*16*XLD + (2*ks+1)*8, XLD);
            wmma::load_matrix_sync(fbo, s_w1 + (2*ks+1)*8*W1LD + c1*16, W1LD);
            wmma::mma_sync(a1e, fae, fbe, a1e);
            wmma::mma_sync(a1o, fao, fbo, a1o);
        }
#pragma unroll
        for (int e = 0; e < a1e.num_elements; e++) a1e.x[e] += a1o.x[e];
        wmma::store_matrix_sync(s_h + r1*16*HLD + c1*16, a1e, HLD, wmma::mem_row_major);
        __syncwarp();
        {   // bias + exact GELU on own tile, tf32 write
            float* tb = s_h + r1*16*HLD + c1*16;
            const float* bp = b1 + h0 + c1*16;
#pragma unroll
            for (int e = lane; e < 256; e += 32){
                int rr2 = e >> 4, cc = e & 15;
                float v = tb[rr2*HLD + cc] + bp[cc];
                tb[rr2*HLD + cc] = wmma::__float_to_tf32(gelu_exact(v));
            }
        }
        cp_wait<0>();      // w2 arrived (hidden behind GEMM1 + GELU)
        __syncthreads();   // gelu'd s_h + w2 visible

        // GEMM2: acc2 += H[64,32] @ W2c[32,192]; 2x3 tiles/warp
#pragma unroll
        for (int ks = 0; ks < 4; ks++){
            FragA fa0, fa1;
            wmma::load_matrix_sync(fa0, s_h + (2*rp  )*16*HLD + ks*8, HLD);
            wmma::load_matrix_sync(fa1, s_h + (2*rp+1)*16*HLD + ks*8, HLD);
#pragma unroll
            for (int j = 0; j < 3; j++){
                FragB fb; wmma::load_matrix_sync(fb, s_w2 + ks*8*W2LD + (3*cp + j)*16, W2LD);
                wmma::mma_sync(acc2[0][j], fa0, fb, acc2[0][j]);
                wmma::mma_sync(acc2[1][j], fa1, fb, acc2[1][j]);
            }
        }
    }
    __syncthreads();   // last GEMM1 readers of s_xn done

    // epilogue: acc2 -> s_xn (overwrite), then residual + bias, coalesced out
#pragma unroll
    for (int i = 0; i < 2; i++)
#pragma unroll
        for (int j = 0; j < 3; j++)
            wmma::store_matrix_sync(s_xn + (2*rp+i)*16*XLD + (3*cp+j)*16, acc2[i][j],
                                    XLD, wmma::mem_row_major);
    __syncthreads();

    float* ob = out + tok0 * DIMC;
    for (int idx = t; idx < TM*48; idx += ML_THREADS){
        int r = idx / 48, c4 = idx - r*48;
        float4 a  = *(float4*)(s_xn + r*XLD + c4*4);
        float4 xr = *(const float4*)(xb + (size_t)r*DIMC + c4*4);
        float4 bb = *(const float4*)(b2 + c4*4);
        a.x += xr.x + bb.x; a.y += xr.y + bb.y;
        a.z += xr.z + bb.z; a.w += xr.w + bb.w;
        *(float4*)(ob + (size_t)r*DIMC + c4*4) = a;
    }
}

// =====================================================================
// launch
// =====================================================================
extern "C" void kernel_launch(void* const* d_in, const int* in_sizes, int n_in,
                              void* d_out, int out_size)
{
    (void)in_sizes; (void)n_in; (void)out_size;
    const float* x      = (const float*)d_in[0];
    const float* qkv_w  = (const float*)d_in[1];
    const float* qkv_b  = (const float*)d_in[2];
    const float* proj_w = (const float*)d_in[3];
    const float* proj_b = (const float*)d_in[4];
    const float* g1     = (const float*)d_in[5];
    const float* be1    = (const float*)d_in[6];
    const float* g2     = (const float*)d_in[7];
    const float* be2    = (const float*)d_in[8];
    const float* w1     = (const float*)d_in[9];
    const float* b1     = (const float*)d_in[10];
    const float* w2     = (const float*)d_in[11];
    const float* b2     = (const float*)d_in[12];
    float* out = (float*)d_out;

    cudaFuncSetAttribute(attn_kernel, cudaFuncAttributeMaxDynamicSharedMemorySize, ATT_SMEM_BYTES);
    cudaFuncSetAttribute(mlp_kernel,  cudaFuncAttributeMaxDynamicSharedMemorySize, MLP_SMEM_BYTES);

    round_weights_kernel<<<RW_BLOCKS, RW_THREADS>>>(w1, w2, qkv_w, proj_w);
    attn_kernel<<<NBLKS, AT_THREADS, ATT_SMEM_BYTES>>>(x, qkv_b, proj_b, g1, be1);
    mlp_kernel<<<(BATCH*NTOK)/TM, ML_THREADS, MLP_SMEM_BYTES>>>(g2, be2, b1, b2, out);
}

// round 14
// speedup vs baseline: 2.7418x; 2.3505x over previous
#include <cuda_runtime.h>
#include <cuda_fp16.h>
#include <cstdint>
#include <math.h>
#include <mma.h>

using namespace nvcuda;

// ---------------- problem constants ----------------
#define DIMC   192
#define HW     56
#define WSZ    7
#define SHIFT  3
#define NHEADS 6
#define HD     32
#define HIDDEN 768
#define BATCH  32
#define NTOK   (HW*HW)          // 3136
#define NBLKS  (BATCH*64)       // 2048 windows
#define NTOKW  49

// ---------------- scratch ----------------
__device__ float g_xattn[(size_t)BATCH * NTOK * DIMC];

// fp16 weight copies (filled once per launch)
#define NW1   (DIMC*HIDDEN)
#define NW2   (HIDDEN*DIMC)
#define NQKV  (DIMC*3*DIMC)
#define NPROJ (DIMC*DIMC)
__device__ __align__(16) __half g_w1h[NW1];
__device__ __align__(16) __half g_w2h[NW2];
__device__ __align__(16) __half g_qkvh[NQKV];
__device__ __align__(16) __half g_projh[NPROJ];

// ---------------- helpers ----------------
__device__ __forceinline__ float warp_sum(float v){
#pragma unroll
    for (int o = 16; o; o >>= 1) v += __shfl_xor_sync(0xffffffffu, v, o);
    return v;
}
__device__ __forceinline__ float warp_max(float v){
#pragma unroll
    for (int o = 16; o; o >>= 1) v = fmaxf(v, __shfl_xor_sync(0xffffffffu, v, o));
    return v;
}
__device__ __forceinline__ float gelu_exact(float x){
    return 0.5f * x * (1.0f + erff(x * 0.70710678118654752440f));
}

// cp.async helpers
__device__ __forceinline__ void cp_async16(void* smem, const void* gmem){
    unsigned int s = (unsigned int)__cvta_generic_to_shared(smem);
    asm volatile("cp.async.cg.shared.global [%0], [%1], 16;\n" :: "r"(s), "l"(gmem));
}
__device__ __forceinline__ void cp_commit(){
    asm volatile("cp.async.commit_group;\n");
}
template<int N>
__device__ __forceinline__ void cp_wait(){
    asm volatile("cp.async.wait_group %0;\n" :: "n"(N));
}

typedef wmma::fragment<wmma::matrix_a, 16, 16, 16, __half, wmma::row_major> FA;
typedef wmma::fragment<wmma::matrix_b, 16, 16, 16, __half, wmma::row_major> FB;
typedef wmma::fragment<wmma::matrix_b, 16, 16, 16, __half, wmma::col_major> FBt;
typedef wmma::fragment<wmma::accumulator, 16, 16, 16, float> FC;

// =====================================================================
// Kernel 0: convert all weights to fp16 once.
// =====================================================================
#define RW_THREADS 256
#define RW_BLOCKS  432   // 110592 float4-groups / 256

__global__ __launch_bounds__(RW_THREADS)
void prep_kernel(const float* __restrict__ w1, const float* __restrict__ w2,
                 const float* __restrict__ qkv_w, const float* __restrict__ proj_w)
{
    int i = blockIdx.x * RW_THREADS + threadIdx.x;   // 4-elem group index
    const float* src; __half* dst;
    if (i < NW1/4){ src = w1; dst = g_w1h; }
    else if ((i -= NW1/4) < NW2/4){ src = w2; dst = g_w2h; }
    else if ((i -= NW2/4) < NQKV/4){ src = qkv_w; dst = g_qkvh; }
    else if ((i -= NQKV/4) < NPROJ/4){ src = proj_w; dst = g_projh; }
    else return;
    float4 v = ((const float4*)src)[i];
    __half2* d = (__half2*)dst;
    d[2*i  ] = __floats2half2_rn(v.x, v.y);
    d[2*i+1] = __floats2half2_rn(v.z, v.w);
}

// =====================================================================
// Kernel 1: shifted-window attention, fp16 wmma, one CTA per window,
// 384 threads, 2x2 warp tiles, register-prefetch weight stream.
// Half strides ≡8 mod 16 (200/72) -> conflict-free ldmatrix.
// =====================================================================
#define AT_THREADS 384
#define FLD  196     // float scratch stride
#define AHL  200     // half stride (192-wide buffers)
#define SHL  72      // half stride (scores)

#define OFF_FS 0                     // float [64][196] = 12544 floats
#define OFF_XH 12544                 // half  [64][200] = 6400 floats
#define OFF_QH (OFF_XH + 6400)
#define OFF_KH (OFF_QH + 6400)
#define OFF_VH (OFF_KH + 6400)
#define OFF_SH (OFF_VH + 6400)       // half [3][64][72] = 6912 floats
#define OFF_BH (OFF_SH + 6912)       // half [32][200]   = 3200 floats
#define ATT_SMEM_FLOATS (OFF_BH + 3200)      // 48256
#define ATT_SMEM_BYTES  (ATT_SMEM_FLOATS*4)  // 193024

__global__ __launch_bounds__(AT_THREADS)
void attn_kernel(const float* __restrict__ x,
                 const float* __restrict__ qkv_b,
                 const float* __restrict__ proj_b,
                 const float* __restrict__ g1, const float* __restrict__ be1)
{
    extern __shared__ float sm[];
    float*  FS = sm + OFF_FS;
    __half* xh = (__half*)(sm + OFF_XH);   // LN'd input; later O (half)
    __half* qh = (__half*)(sm + OFF_QH);
    __half* kh = (__half*)(sm + OFF_KH);
    __half* vh = (__half*)(sm + OFF_VH);
    __half* Sh = (__half*)(sm + OFF_SH);
    __half* bh = (__half*)(sm + OFF_BH);   // weight staging

    const int t   = threadIdx.x;
    const int wid = t >> 5, lane = t & 31;
    const int blk = blockIdx.x;
    const int b   = blk >> 6;
    const int win = blk & 63;
    const int wr  = win >> 3, wc = win & 7;

    const float* xb = x + (size_t)b * NTOK * DIMC;

    // staging coords: 768 uint4 per chunk / 384 threads = 2 each
    int prow[2], pc8[2];
#pragma unroll
    for (int i = 0; i < 2; i++){
        int idx = t + i*AT_THREADS;
        prow[i] = idx / 24; pc8[i] = idx - prow[i]*24;
    }
    uint4 pf[2];
#pragma unroll
    for (int i = 0; i < 2; i++)   // chunk 0: qkv m=0, kc=0
        pf[i] = *(const uint4*)(g_qkvh + (size_t)prow[i]*(3*DIMC) + pc8[i]*8);

    // zero all half buffers (xh..Sh): floats [OFF_XH, OFF_BH) = 32512 = 8128 float4
    {
        float4 zf = make_float4(0.f,0.f,0.f,0.f);
        float4* zp = (float4*)(sm + OFF_XH);
        for (int idx = t; idx < 8128; idx += AT_THREADS) zp[idx] = zf;
    }

    // gather with cyclic shift (roll -3,-3) into FS
    for (int idx = t; idx < NTOKW*48; idx += AT_THREADS){
        int row = idx / 48, c4 = idx - row*48;
        int ti = row / WSZ, tj = row - ti*WSZ;
        int sr = wr*WSZ + ti + SHIFT; if (sr >= HW) sr -= HW;
        int sc = wc*WSZ + tj + SHIFT; if (sc >= HW) sc -= HW;
        *(float4*)(FS + row*FLD + c4*4) =
            *(const float4*)(xb + (size_t)(sr*HW + sc)*DIMC + c4*4);
    }
    __syncthreads();

    // LN1: read FS, write half xh (rows < 49; pad rows stay 0)
    for (int r = wid; r < NTOKW; r += 12){
        float s = 0.f, s2 = 0.f;
#pragma unroll
        for (int c = lane; c < DIMC; c += 32){
            float v = FS[r*FLD + c]; s += v; s2 += v*v;
        }
        s = warp_sum(s); s2 = warp_sum(s2);
        float mu = s * (1.0f/DIMC);
        float rs = rsqrtf(s2*(1.0f/DIMC) - mu*mu + 1e-5f);
#pragma unroll
        for (int c = lane; c < DIMC; c += 32){
            float v = (FS[r*FLD + c] - mu)*rs*g1[c] + be1[c];
            xh[r*AHL + c] = __float2half_rn(v);
        }
    }

    // 2x2 warp tiling for [64,192] GEMMs (12 warps, 48 tiles)
    const int rt0 = (wid / 6) * 2;
    const int cgi = wid % 6;

    int ci = 0;   // weight chunk stream: 18 qkv + 6 proj

    // ---- QKV ----
    for (int m = 0; m < 3; m++){
        FC acc[2][2];
#pragma unroll
        for (int i = 0; i < 2; i++)
#pragma unroll
            for (int j = 0; j < 2; j++) wmma::fill_fragment(acc[i][j], 0.f);

        for (int kc = 0; kc < 6; kc++){
            __syncthreads();   // prev chunk readers of bh done (iter0: LN order)
#pragma unroll
            for (int i = 0; i < 2; i++)
                *(uint4*)(bh + prow[i]*AHL + pc8[i]*8) = pf[i];
            ci++;
            if (ci < 18){
                int m2 = ci / 6, kc2 = ci - m2*6;
                const __half* base = g_qkvh + (size_t)(kc2*32)*(3*DIMC) + m2*DIMC;
#pragma unroll
                for (int i = 0; i < 2; i++)
                    pf[i] = *(const uint4*)(base + (size_t)prow[i]*(3*DIMC) + pc8[i]*8);
            } else if (ci < 24){
                int kc2 = ci - 18;
                const __half* base = g_projh + (size_t)(kc2*32)*DIMC;
#pragma unroll
                for (int i = 0; i < 2; i++)
                    pf[i] = *(const uint4*)(base + (size_t)prow[i]*DIMC + pc8[i]*8);
            }
            __syncthreads();
#pragma unroll
            for (int ks = 0; ks < 2; ks++){
                FA fa0, fa1;
                wmma::load_matrix_sync(fa0, xh + (rt0  )*16*AHL + kc*32 + ks*16, AHL);
                wmma::load_matrix_sync(fa1, xh + (rt0+1)*16*AHL + kc*32 + ks*16, AHL);
                FB fb0, fb1;
                wmma::load_matrix_sync(fb0, bh + ks*16*AHL + cgi*16, AHL);
                wmma::load_matrix_sync(fb1, bh + ks*16*AHL + (cgi+6)*16, AHL);
                wmma::mma_sync(acc[0][0], fa0, fb0, acc[0][0]);
                wmma::mma_sync(acc[0][1], fa0, fb1, acc[0][1]);
                wmma::mma_sync(acc[1][0], fa1, fb0, acc[1][0]);
                wmma::mma_sync(acc[1][1], fa1, fb1, acc[1][1]);
            }
        }
        // accum -> FS
#pragma unroll
        for (int i = 0; i < 2; i++){
            wmma::store_matrix_sync(FS + (rt0+i)*16*FLD + cgi*16,     acc[i][0], FLD, wmma::mem_row_major);
            wmma::store_matrix_sync(FS + (rt0+i)*16*FLD + (cgi+6)*16, acc[i][1], FLD, wmma::mem_row_major);
        }
        __syncthreads();
        // bias + half-cvt into qh/kh/vh (rows < 49 only; pads stay 0)
        {
            __half* dst = (m == 0) ? qh : (m == 1) ? kh : vh;
            const float* bb = qkv_b + m*DIMC;
            for (int idx = t; idx < NTOKW*DIMC; idx += AT_THREADS){
                int r = idx / DIMC, c = idx - r*DIMC;
                dst[r*AHL + c] = __float2half_rn(FS[r*FLD + c] + bb[c]);
            }
        }
        // next m's kc-top sync orders these writes + FS reads
    }
    __syncthreads();

    // ---- head groups of 3 ----
    for (int g = 0; g < 2; g++){
        // S = scale * Q K^T : 48 tiles, 4 per warp; f32 accum -> FS[64][192]
#pragma unroll
        for (int i = 0; i < 4; i++){
            int tt = wid + 12*i;
            int hh = tt >> 4, rem = tt & 15;
            int ti = rem >> 2, tj = rem & 3;
            int h = 3*g + hh;
            FC sacc; wmma::fill_fragment(sacc, 0.f);
#pragma unroll
            for (int ks = 0; ks < 2; ks++){
                FA fa;  wmma::load_matrix_sync(fa, qh + h*HD + ti*16*AHL + ks*16, AHL);
                FBt fb; wmma::load_matrix_sync(fb, kh + h*HD + tj*16*AHL + ks*16, AHL);
                wmma::mma_sync(sacc, fa, fb, sacc);
            }
#pragma unroll
            for (int e = 0; e < sacc.num_elements; e++)
                sacc.x[e] *= 0.17677669529663688110f;
            wmma::store_matrix_sync(FS + ti*16*FLD + hh*64 + tj*16, sacc, FLD,
                                    wmma::mem_row_major);
        }
        __syncthreads();

        // softmax: FS float -> Sh half (rows<49, cols<49; pads stay 0)
        for (int rr = wid; rr < 3*NTOKW; rr += 12){
            int hh = rr / NTOKW, r = rr - hh*NTOKW;
            const float* row = FS + r*FLD + hh*64;
            __half* orow = Sh + hh*64*SHL + r*SHL;
            float v0 = (lane      < NTOKW) ? row[lane     ] : -1e30f;
            float v1 = (lane + 32 < NTOKW) ? row[lane + 32] : -1e30f;
            float m  = warp_max(fmaxf(v0, v1));
            float e0 = (lane      < NTOKW) ? __expf(v0 - m) : 0.f;
            float e1 = (lane + 32 < NTOKW) ? __expf(v1 - m) : 0.f;
            float inv = 1.0f / warp_sum(e0 + e1);
            if (lane      < NTOKW) orow[lane     ] = __float2half_rn(e0 * inv);
            if (lane + 32 < NTOKW) orow[lane + 32] = __float2half_rn(e1 * inv);
        }
        __syncthreads();

        // PV: O_h[64,32] = P @ V_h; 24 tiles, 2 per warp; accum -> FS[64][96]
#pragma unroll
        for (int i = 0; i < 2; i++){
            int tt = wid + 12*i;
            int hh = tt >> 3, rem = tt & 7;
            int ti = rem >> 1, tj = rem & 1;
            int h = 3*g + hh;
            FC oacc; wmma::fill_fragment(oacc, 0.f);
#pragma unroll
            for (int ks = 0; ks < 4; ks++){
                FA fa; wmma::load_matrix_sync(fa, Sh + hh*64*SHL + ti*16*SHL + ks*16, SHL);
                FB fb; wmma::load_matrix_sync(fb, vh + h*HD + ks*16*AHL + tj*16, AHL);
                wmma::mma_sync(oacc, fa, fb, oacc);
            }
            wmma::store_matrix_sync(FS + ti*16*FLD + hh*32 + tj*16, oacc, FLD,
                                    wmma::mem_row_major);
        }
        __syncthreads();

        // cvt O -> xh (half), cols [96g, 96g+96)
        for (int idx = t; idx < NTOKW*96; idx += AT_THREADS){
            int r = idx / 96, cc = idx - r*96;
            xh[r*AHL + g*96 + cc] = __float2half_rn(FS[r*FLD + cc]);
        }
        __syncthreads();
    }

    // ---- proj: A = xh (O half) ----
    {
        FC acc[2][2];
#pragma unroll
        for (int i = 0; i < 2; i++)
#pragma unroll
            for (int j = 0; j < 2; j++) wmma::fill_fragment(acc[i][j], 0.f);

        for (int kc = 0; kc < 6; kc++){
            __syncthreads();
#pragma unroll
            for (int i = 0; i < 2; i++)
                *(uint4*)(bh + prow[i]*AHL + pc8[i]*8) = pf[i];
            ci++;
            if (ci < 24){
                int kc2 = ci - 18;
                const __half* base = g_projh + (size_t)(kc2*32)*DIMC;
#pragma unroll
                for (int i = 0; i < 2; i++)
                    pf[i] = *(const uint4*)(base + (size_t)prow[i]*DIMC + pc8[i]*8);
            }
            __syncthreads();
#pragma unroll
            for (int ks = 0; ks < 2; ks++){
                FA fa0, fa1;
                wmma::load_matrix_sync(fa0, xh + (rt0  )*16*AHL + kc*32 + ks*16, AHL);
                wmma::load_matrix_sync(fa1, xh + (rt0+1)*16*AHL + kc*32 + ks*16, AHL);
                FB fb0, fb1;
                wmma::load_matrix_sync(fb0, bh + ks*16*AHL + cgi*16, AHL);
                wmma::load_matrix_sync(fb1, bh + ks*16*AHL + (cgi+6)*16, AHL);
                wmma::mma_sync(acc[0][0], fa0, fb0, acc[0][0]);
                wmma::mma_sync(acc[0][1], fa0, fb1, acc[0][1]);
                wmma::mma_sync(acc[1][0], fa1, fb0, acc[1][0]);
                wmma::mma_sync(acc[1][1], fa1, fb1, acc[1][1]);
            }
        }
#pragma unroll
        for (int i = 0; i < 2; i++){
            wmma::store_matrix_sync(FS + (rt0+i)*16*FLD + cgi*16,     acc[i][0], FLD, wmma::mem_row_major);
            wmma::store_matrix_sync(FS + (rt0+i)*16*FLD + (cgi+6)*16, acc[i][1], FLD, wmma::mem_row_major);
        }
        __syncthreads();

        // scatter (roll +3,+3) + proj bias
        float* ob = g_xattn + (size_t)b * NTOK * DIMC;
        for (int idx = t; idx < NTOKW*48; idx += AT_THREADS){
            int row = idx / 48, c4 = idx - row*48;
            int ti2 = row / WSZ, tj2 = row - ti2*WSZ;
            int sr = wr*WSZ + ti2 + SHIFT; if (sr >= HW) sr -= HW;
            int sc = wc*WSZ + tj2 + SHIFT; if (sc >= HW) sc -= HW;
            float4 v  = *(float4*)(FS + row*FLD + c4*4);
            float4 pb = *(const float4*)(proj_b + c4*4);
            v.x += pb.x; v.y += pb.y; v.z += pb.z; v.w += pb.w;
            *(float4*)(ob + (size_t)(sr*HW + sc)*DIMC + c4*4) = v;
        }
    }
}

// =====================================================================
// Kernel 2: fused MLP, fp16 wmma, 2 CTAs/SM, TM=64/256 threads.
// =====================================================================
#define ML_THREADS 256
#define TM 64
#define TH 32
#define XHL  200   // half stride, LN'd x
#define W1L  40    // half stride, w1 chunk
#define HFL  68    // float stride, H accum scratch
#define HHL  72    // half stride, gelu'd H
#define W2L  200   // half stride, w2 chunk
#define MO_XNH 0                      // half [64][200]  = 6400 floats
#define MO_W1H 6400                   // half [192][40]  = 3840
#define MO_HF  10240                  // float [64][68]  = 4352
#define MO_HH  14592                  // half [64][72]   = 2304
#define MO_W2H 16896                  // half [32][200]  = 3200
#define MO_EPI 6400                   // float [64][196] (overlays W1H..W2H)
#define MLP_SMEM_FLOATS 20096
#define MLP_SMEM_BYTES  (MLP_SMEM_FLOATS*4)   // 80384 -> 2 CTAs/SM

__global__ __launch_bounds__(ML_THREADS, 2)
void mlp_kernel(const float* __restrict__ g2, const float* __restrict__ be2,
                const float* __restrict__ b1, const float* __restrict__ b2,
                float* __restrict__ out)
{
    extern __shared__ float sm[];
    __half* xnh = (__half*)(sm + MO_XNH);
    __half* w1h = (__half*)(sm + MO_W1H);
    float*  hf  = sm + MO_HF;
    __half* hhb = (__half*)(sm + MO_HH);
    __half* w2h = (__half*)(sm + MO_W2H);
    float*  epi = sm + MO_EPI;

    const int t = threadIdx.x;
    const int wid = t >> 5, lane = t & 31;
    const size_t tok0 = (size_t)blockIdx.x * TM;
    const float* xb = g_xattn + tok0 * DIMC;

    // load x into epi (free pre-loop), LN -> half xnh
    for (int idx = t; idx < TM*48; idx += ML_THREADS){
        int r = idx / 48, c4 = idx - r*48;
        *(float4*)(epi + r*FLD + c4*4) = *(const float4*)(xb + (size_t)r*DIMC + c4*4);
    }
    __syncthreads();
    for (int r = wid; r < TM; r += 8){
        float s = 0.f, s2 = 0.f;
#pragma unroll
        for (int c = lane; c < DIMC; c += 32){
            float v = epi[r*FLD + c]; s += v; s2 += v*v;
        }
        s = warp_sum(s); s2 = warp_sum(s2);
        float mu = s * (1.0f/DIMC);
        float rs = rsqrtf(s2*(1.0f/DIMC) - mu*mu + 1e-5f);
#pragma unroll
        for (int c = lane; c < DIMC; c += 32){
            float v = (epi[r*FLD + c] - mu)*rs*g2[c] + be2[c];
            xnh[r*XHL + c] = __float2half_rn(v);
        }
    }

    const int r1 = wid & 3, c1 = wid >> 2;     // GEMM1: 4x2 tile grid
    const int rp = wid & 1, cp = wid >> 1;     // GEMM2: 2x3 tiles/warp

    FC acc2[2][3];
#pragma unroll
    for (int i = 0; i < 2; i++)
#pragma unroll
        for (int j = 0; j < 3; j++) wmma::fill_fragment(acc2[i][j], 0.f);

    for (int hc = 0; hc < 24; hc++){
        const int h0 = hc * TH;
        __syncthreads();   // prev chunk readers done (iter0: LN reads of epi done)

        // stage w1 [192][32] halfs (group 1): 768 uint4, 3/thread
#pragma unroll
        for (int i = 0; i < 3; i++){
            int id = t + i*ML_THREADS;
            int row = id >> 2, c8 = id & 3;
            cp_async16(w1h + row*W1L + c8*8, g_w1h + (size_t)row*HIDDEN + h0 + c8*8);
        }
        cp_commit();
        // stage w2 [32][192] halfs (group 2)
#pragma unroll
        for (int i = 0; i < 3; i++){
            int id = t + i*ML_THREADS;
            int row = id / 24, c8 = id - row*24;
            cp_async16(w2h + row*W2L + c8*8, g_w2h + (size_t)(h0 + row)*DIMC + c8*8);
        }
        cp_commit();

        cp_wait<1>();      // w1 arrived
        __syncthreads();

        // GEMM1: H[64,32] = Xn[64,192] @ W1c ; 12 mma as 2 chains of 6
        FC a1e, a1o;
        wmma::fill_fragment(a1e, 0.f);
        wmma::fill_fragment(a1o, 0.f);
#pragma unroll
        for (int ks = 0; ks < 6; ks++){
            FA fae, fao; FB fbe, fbo;
            wmma::load_matrix_sync(fae, xnh + r1*16*XHL + (2*ks  )*16, XHL);
            wmma::load_matrix_sync(fbe, w1h + (2*ks  )*16*W1L + c1*16, W1L);
            wmma::load_matrix_sync(fao, xnh + r1*16*XHL + (2*ks+1)*16, XHL);
            wmma::load_matrix_sync(fbo, w1h + (2*ks+1)*16*W1L + c1*16, W1L);
            wmma::mma_sync(a1e, fae, fbe, a1e);
            wmma::mma_sync(a1o, fao, fbo, a1o);
        }
#pragma unroll
        for (int e = 0; e < a1e.num_elements; e++) a1e.x[e] += a1o.x[e];
        wmma::store_matrix_sync(hf + r1*16*HFL + c1*16, a1e, HFL, wmma::mem_row_major);
        __syncwarp();
        {   // bias + exact GELU on own tile -> half
            float*  tf = hf  + r1*16*HFL + c1*16;
            __half* th = hhb + r1*16*HHL + c1*16;
            const float* bp = b1 + h0 + c1*16;
#pragma unroll
            for (int e = lane; e < 256; e += 32){
                int rr = e >> 4, cc = e & 15;
                th[rr*HHL + cc] = __float2half_rn(gelu_exact(tf[rr*HFL + cc] + bp[cc]));
            }
        }
        cp_wait<0>();      // w2 arrived (hidden behind GEMM1 + GELU)
        __syncthreads();

        // GEMM2: acc2 += H[64,32] @ W2c[32,192] ; K=32 -> 2 k-steps
#pragma unroll
        for (int ks = 0; ks < 2; ks++){
            FA fa0, fa1;
            wmma::load_matrix_sync(fa0, hhb + (2*rp  )*16*HHL + ks*16, HHL);
            wmma::load_matrix_sync(fa1, hhb + (2*rp+1)*16*HHL + ks*16, HHL);
#pragma unroll
            for (int j = 0; j < 3; j++){
                FB fb; wmma::load_matrix_sync(fb, w2h + ks*16*W2L + (3*cp + j)*16, W2L);
                wmma::mma_sync(acc2[0][j], fa0, fb, acc2[0][j]);
                wmma::mma_sync(acc2[1][j], fa1, fb, acc2[1][j]);
            }
        }
    }
    __syncthreads();

    // epilogue: acc2 -> epi (overlays weight buffers, all dead)
#pragma unroll
    for (int i = 0; i < 2; i++)
#pragma unroll
        for (int j = 0; j < 3; j++)
            wmma::store_matrix_sync(epi + (2*rp+i)*16*FLD + (3*cp+j)*16, acc2[i][j],
                                    FLD, wmma::mem_row_major);
    __syncthreads();

    float* ob = out + tok0 * DIMC;
    for (int idx = t; idx < TM*48; idx += ML_THREADS){
        int r = idx / 48, c4 = idx - r*48;
        float4 a  = *(float4*)(epi + r*FLD + c4*4);
        float4 xr = *(const float4*)(xb + (size_t)r*DIMC + c4*4);
        float4 bb = *(const float4*)(b2 + c4*4);
        a.x += xr.x + bb.x; a.y += xr.y + bb.y;
        a.z += xr.z + bb.z; a.w += xr.w + bb.w;
        *(float4*)(ob + (size_t)r*DIMC + c4*4) = a;
    }
}

// =====================================================================
// launch
// =====================================================================
extern "C" void kernel_launch(void* const* d_in, const int* in_sizes, int n_in,
                              void* d_out, int out_size)
{
    (void)in_sizes; (void)n_in; (void)out_size;
    const float* x      = (const float*)d_in[0];
    const float* qkv_w  = (const float*)d_in[1];
    const float* qkv_b  = (const float*)d_in[2];
    const float* proj_w = (const float*)d_in[3];
    const float* proj_b = (const float*)d_in[4];
    const float* g1     = (const float*)d_in[5];
    const float* be1    = (const float*)d_in[6];
    const float* g2     = (const float*)d_in[7];
    const float* be2    = (const float*)d_in[8];
    const float* w1     = (const float*)d_in[9];
    const float* b1     = (const float*)d_in[10];
    const float* w2     = (const float*)d_in[11];
    const float* b2     = (const float*)d_in[12];
    float* out = (float*)d_out;

    cudaFuncSetAttribute(attn_kernel, cudaFuncAttributeMaxDynamicSharedMemorySize, ATT_SMEM_BYTES);
    cudaFuncSetAttribute(mlp_kernel,  cudaFuncAttributeMaxDynamicSharedMemorySize, MLP_SMEM_BYTES);

    prep_kernel<<<RW_BLOCKS, RW_THREADS>>>(w1, w2, qkv_w, proj_w);
    attn_kernel<<<NBLKS, AT_THREADS, ATT_SMEM_BYTES>>>(x, qkv_b, proj_b, g1, be1);
    mlp_kernel<<<(BATCH*NTOK)/TM, ML_THREADS, MLP_SMEM_BYTES>>>(g2, be2, b1, b2, out);
}

// round 16
// speedup vs baseline: 2.9155x; 1.0634x over previous
#include <cuda_runtime.h>
#include <cuda_fp16.h>
#include <cstdint>
#include <math.h>
#include <mma.h>

using namespace nvcuda;

// ---------------- problem constants ----------------
#define DIMC   192
#define HW     56
#define WSZ    7
#define SHIFT  3
#define NHEADS 6
#define HD     32
#define HIDDEN 768
#define BATCH  32
#define NTOK   (HW*HW)          // 3136
#define NBLKS  (BATCH*64)       // 2048 windows
#define NTOKW  49

// ---------------- scratch ----------------
__device__ float g_xattn[(size_t)BATCH * NTOK * DIMC];

// fp16 weight copies (filled once per launch)
#define NW1   (DIMC*HIDDEN)
#define NW2   (HIDDEN*DIMC)
#define NQKV  (DIMC*3*DIMC)
#define NPROJ (DIMC*DIMC)
__device__ __align__(16) __half g_w1h[NW1];
__device__ __align__(16) __half g_w2h[NW2];
__device__ __align__(16) __half g_qkvh[NQKV];
__device__ __align__(16) __half g_projh[NPROJ];

// ---------------- helpers ----------------
__device__ __forceinline__ float warp_sum(float v){
#pragma unroll
    for (int o = 16; o; o >>= 1) v += __shfl_xor_sync(0xffffffffu, v, o);
    return v;
}
__device__ __forceinline__ float warp_max(float v){
#pragma unroll
    for (int o = 16; o; o >>= 1) v = fmaxf(v, __shfl_xor_sync(0xffffffffu, v, o));
    return v;
}
__device__ __forceinline__ float gelu_exact(float x){
    return 0.5f * x * (1.0f + erff(x * 0.70710678118654752440f));
}

// cp.async helpers
__device__ __forceinline__ void cp_async16(void* smem, const void* gmem){
    unsigned int s = (unsigned int)__cvta_generic_to_shared(smem);
    asm volatile("cp.async.cg.shared.global [%0], [%1], 16;\n" :: "r"(s), "l"(gmem));
}
__device__ __forceinline__ void cp_commit(){
    asm volatile("cp.async.commit_group;\n");
}
template<int N>
__device__ __forceinline__ void cp_wait(){
    asm volatile("cp.async.wait_group %0;\n" :: "n"(N));
}

typedef wmma::fragment<wmma::matrix_a, 16, 16, 16, __half, wmma::row_major> FA;
typedef wmma::fragment<wmma::matrix_b, 16, 16, 16, __half, wmma::row_major> FB;
typedef wmma::fragment<wmma::matrix_b, 16, 16, 16, __half, wmma::col_major> FBt;
typedef wmma::fragment<wmma::accumulator, 16, 16, 16, float> FC;

// =====================================================================
// Kernel 0: convert all weights to fp16 once.
// =====================================================================
#define RW_THREADS 256
#define RW_BLOCKS  432   // 110592 4-elem groups / 256

__global__ __launch_bounds__(RW_THREADS)
void prep_kernel(const float* __restrict__ w1, const float* __restrict__ w2,
                 const float* __restrict__ qkv_w, const float* __restrict__ proj_w)
{
    int i = blockIdx.x * RW_THREADS + threadIdx.x;   // 4-elem group index
    const float* src; __half* dst;
    if (i < NW1/4){ src = w1; dst = g_w1h; }
    else if ((i -= NW1/4) < NW2/4){ src = w2; dst = g_w2h; }
    else if ((i -= NW2/4) < NQKV/4){ src = qkv_w; dst = g_qkvh; }
    else if ((i -= NQKV/4) < NPROJ/4){ src = proj_w; dst = g_projh; }
    else return;
    float4 v = ((const float4*)src)[i];
    __half2* d = (__half2*)dst;
    d[2*i  ] = __floats2half2_rn(v.x, v.y);
    d[2*i+1] = __floats2half2_rn(v.z, v.w);
}

// =====================================================================
// Kernel 1: shifted-window attention, fp16 wmma, one CTA per window,
// 384 threads, 2x2 warp tiles. 64-row weight staging (12 chunks total:
// 9 qkv + 3 proj) -> half the staging barriers of R14.
// =====================================================================
#define AT_THREADS 384
#define FLD  196     // float scratch stride
#define AHL  200     // half stride (192-wide buffers)
#define SHL  72      // half stride (scores)

#define OFF_FS 0                     // float [64][196] = 12544 floats
#define OFF_XH 12544                 // half  [64][200] = 6400 floats
#define OFF_QH (OFF_XH + 6400)
#define OFF_KH (OFF_QH + 6400)
#define OFF_VH (OFF_KH + 6400)
#define OFF_SH (OFF_VH + 6400)       // half [3][64][72] = 6912 floats
#define OFF_BH (OFF_SH + 6912)       // half [64][200]   = 6400 floats
#define ATT_SMEM_FLOATS (OFF_BH + 6400)      // 51456
#define ATT_SMEM_BYTES  (ATT_SMEM_FLOATS*4)  // 205824

__global__ __launch_bounds__(AT_THREADS)
void attn_kernel(const float* __restrict__ x,
                 const float* __restrict__ qkv_b,
                 const float* __restrict__ proj_b,
                 const float* __restrict__ g1, const float* __restrict__ be1)
{
    extern __shared__ float sm[];
    float*  FS = sm + OFF_FS;
    __half* xh = (__half*)(sm + OFF_XH);   // LN'd input; later O (half)
    __half* qh = (__half*)(sm + OFF_QH);
    __half* kh = (__half*)(sm + OFF_KH);
    __half* vh = (__half*)(sm + OFF_VH);
    __half* Sh = (__half*)(sm + OFF_SH);
    __half* bh = (__half*)(sm + OFF_BH);   // weight staging [64][200]

    const int t   = threadIdx.x;
    const int wid = t >> 5, lane = t & 31;
    const int blk = blockIdx.x;
    const int b   = blk >> 6;
    const int win = blk & 63;
    const int wr  = win >> 3, wc = win & 7;

    const float* xb = x + (size_t)b * NTOK * DIMC;

    // staging coords: 64 rows x 192 halfs = 1536 uint4 / 384 threads = 4 each
    int prow[4], pc8[4];
#pragma unroll
    for (int i = 0; i < 4; i++){
        int idx = t + i*AT_THREADS;
        prow[i] = idx / 24; pc8[i] = idx - prow[i]*24;
    }
    uint4 pf[4];
#pragma unroll
    for (int i = 0; i < 4; i++)   // chunk 0: qkv m=0, stage 0
        pf[i] = *(const uint4*)(g_qkvh + (size_t)prow[i]*(3*DIMC) + pc8[i]*8);

    // zero half buffers xh..Sh: floats [OFF_XH, OFF_BH) = 32512 = 8128 float4
    {
        float4 zf = make_float4(0.f,0.f,0.f,0.f);
        float4* zp = (float4*)(sm + OFF_XH);
        for (int idx = t; idx < 8128; idx += AT_THREADS) zp[idx] = zf;
    }

    // gather with cyclic shift (roll -3,-3) into FS
    for (int idx = t; idx < NTOKW*48; idx += AT_THREADS){
        int row = idx / 48, c4 = idx - row*48;
        int ti = row / WSZ, tj = row - ti*WSZ;
        int sr = wr*WSZ + ti + SHIFT; if (sr >= HW) sr -= HW;
        int sc = wc*WSZ + tj + SHIFT; if (sc >= HW) sc -= HW;
        *(float4*)(FS + row*FLD + c4*4) =
            *(const float4*)(xb + (size_t)(sr*HW + sc)*DIMC + c4*4);
    }
    __syncthreads();

    // LN1: read FS, write half xh (rows < 49; pad rows stay 0)
    for (int r = wid; r < NTOKW; r += 12){
        float s = 0.f, s2 = 0.f;
#pragma unroll
        for (int c = lane; c < DIMC; c += 32){
            float v = FS[r*FLD + c]; s += v; s2 += v*v;
        }
        s = warp_sum(s); s2 = warp_sum(s2);
        float mu = s * (1.0f/DIMC);
        float rs = rsqrtf(s2*(1.0f/DIMC) - mu*mu + 1e-5f);
#pragma unroll
        for (int c = lane; c < DIMC; c += 32){
            float v = (FS[r*FLD + c] - mu)*rs*g1[c] + be1[c];
            xh[r*AHL + c] = __float2half_rn(v);
        }
    }

    // 2x2 warp tiling for [64,192] GEMMs (12 warps, 48 tiles)
    const int rt0 = (wid / 6) * 2;
    const int cgi = wid % 6;

    int ci = 0;   // weight chunk stream: 9 qkv + 3 proj (64 k-rows each)

    // ---- QKV ----
    for (int m = 0; m < 3; m++){
        FC acc[2][2];
#pragma unroll
        for (int i = 0; i < 2; i++)
#pragma unroll
            for (int j = 0; j < 2; j++) wmma::fill_fragment(acc[i][j], 0.f);

        for (int kc = 0; kc < 3; kc++){   // 64 k-rows per stage
            __syncthreads();   // prev chunk readers of bh done (iter0: LN order)
#pragma unroll
            for (int i = 0; i < 4; i++)
                *(uint4*)(bh + prow[i]*AHL + pc8[i]*8) = pf[i];
            ci++;
            if (ci < 9){
                int m2 = ci / 3, st = ci - m2*3;
                const __half* base = g_qkvh + (size_t)(st*64)*(3*DIMC) + m2*DIMC;
#pragma unroll
                for (int i = 0; i < 4; i++)
                    pf[i] = *(const uint4*)(base + (size_t)prow[i]*(3*DIMC) + pc8[i]*8);
            } else if (ci < 12){
                int st = ci - 9;
                const __half* base = g_projh + (size_t)(st*64)*DIMC;
#pragma unroll
                for (int i = 0; i < 4; i++)
                    pf[i] = *(const uint4*)(base + (size_t)prow[i]*DIMC + pc8[i]*8);
            }
            __syncthreads();
#pragma unroll
            for (int ks = 0; ks < 4; ks++){
                FA fa0, fa1;
                wmma::load_matrix_sync(fa0, xh + (rt0  )*16*AHL + kc*64 + ks*16, AHL);
                wmma::load_matrix_sync(fa1, xh + (rt0+1)*16*AHL + kc*64 + ks*16, AHL);
                FB fb0, fb1;
                wmma::load_matrix_sync(fb0, bh + ks*16*AHL + cgi*16, AHL);
                wmma::load_matrix_sync(fb1, bh + ks*16*AHL + (cgi+6)*16, AHL);
                wmma::mma_sync(acc[0][0], fa0, fb0, acc[0][0]);
                wmma::mma_sync(acc[0][1], fa0, fb1, acc[0][1]);
                wmma::mma_sync(acc[1][0], fa1, fb0, acc[1][0]);
                wmma::mma_sync(acc[1][1], fa1, fb1, acc[1][1]);
            }
        }
        // accum -> FS
#pragma unroll
        for (int i = 0; i < 2; i++){
            wmma::store_matrix_sync(FS + (rt0+i)*16*FLD + cgi*16,     acc[i][0], FLD, wmma::mem_row_major);
            wmma::store_matrix_sync(FS + (rt0+i)*16*FLD + (cgi+6)*16, acc[i][1], FLD, wmma::mem_row_major);
        }
        __syncthreads();
        // bias + half-cvt into qh/kh/vh (rows < 49 only; pads stay 0)
        {
            __half* dst = (m == 0) ? qh : (m == 1) ? kh : vh;
            const float* bb = qkv_b + m*DIMC;
            for (int idx = t; idx < NTOKW*DIMC; idx += AT_THREADS){
                int r = idx / DIMC, c = idx - r*DIMC;
                dst[r*AHL + c] = __float2half_rn(FS[r*FLD + c] + bb[c]);
            }
        }
        // next m's kc-top sync orders these writes + FS reads
    }
    __syncthreads();

    // ---- head groups of 3 ----
    for (int g = 0; g < 2; g++){
        // S = scale * Q K^T : 48 tiles, 4 per warp; f32 accum -> FS[64][192]
#pragma unroll
        for (int i = 0; i < 4; i++){
            int tt = wid + 12*i;
            int hh = tt >> 4, rem = tt & 15;
            int ti = rem >> 2, tj = rem & 3;
            int h = 3*g + hh;
            FC sacc; wmma::fill_fragment(sacc, 0.f);
#pragma unroll
            for (int ks = 0; ks < 2; ks++){
                FA fa;  wmma::load_matrix_sync(fa, qh + h*HD + ti*16*AHL + ks*16, AHL);
                FBt fb; wmma::load_matrix_sync(fb, kh + h*HD + tj*16*AHL + ks*16, AHL);
                wmma::mma_sync(sacc, fa, fb, sacc);
            }
#pragma unroll
            for (int e = 0; e < sacc.num_elements; e++)
                sacc.x[e] *= 0.17677669529663688110f;
            wmma::store_matrix_sync(FS + ti*16*FLD + hh*64 + tj*16, sacc, FLD,
                                    wmma::mem_row_major);
        }
        __syncthreads();

        // softmax: FS float -> Sh half (rows<49, cols<49; pads stay 0)
        for (int rr = wid; rr < 3*NTOKW; rr += 12){
            int hh = rr / NTOKW, r = rr - hh*NTOKW;
            const float* row = FS + r*FLD + hh*64;
            __half* orow = Sh + hh*64*SHL + r*SHL;
            float v0 = (lane      < NTOKW) ? row[lane     ] : -1e30f;
            float v1 = (lane + 32 < NTOKW) ? row[lane + 32] : -1e30f;
            float m  = warp_max(fmaxf(v0, v1));
            float e0 = (lane      < NTOKW) ? __expf(v0 - m) : 0.f;
            float e1 = (lane + 32 < NTOKW) ? __expf(v1 - m) : 0.f;
            float inv = 1.0f / warp_sum(e0 + e1);
            if (lane      < NTOKW) orow[lane     ] = __float2half_rn(e0 * inv);
            if (lane + 32 < NTOKW) orow[lane + 32] = __float2half_rn(e1 * inv);
        }
        __syncthreads();

        // PV: O_h[64,32] = P @ V_h; 24 tiles, 2 per warp; accum -> FS[64][96]
#pragma unroll
        for (int i = 0; i < 2; i++){
            int tt = wid + 12*i;
            int hh = tt >> 3, rem = tt & 7;
            int ti = rem >> 1, tj = rem & 1;
            int h = 3*g + hh;
            FC oacc; wmma::fill_fragment(oacc, 0.f);
#pragma unroll
            for (int ks = 0; ks < 4; ks++){
                FA fa; wmma::load_matrix_sync(fa, Sh + hh*64*SHL + ti*16*SHL + ks*16, SHL);
                FB fb; wmma::load_matrix_sync(fb, vh + h*HD + ks*16*AHL + tj*16, AHL);
                wmma::mma_sync(oacc, fa, fb, oacc);
            }
            wmma::store_matrix_sync(FS + ti*16*FLD + hh*32 + tj*16, oacc, FLD,
                                    wmma::mem_row_major);
        }
        __syncthreads();

        // cvt O -> xh (half), cols [96g, 96g+96)
        for (int idx = t; idx < NTOKW*96; idx += AT_THREADS){
            int r = idx / 96, cc = idx - r*96;
            xh[r*AHL + g*96 + cc] = __float2half_rn(FS[r*FLD + cc]);
        }
        __syncthreads();
    }

    // ---- proj: A = xh (O half); 3 x 64-row stages ----
    {
        FC acc[2][2];
#pragma unroll
        for (int i = 0; i < 2; i++)
#pragma unroll
            for (int j = 0; j < 2; j++) wmma::fill_fragment(acc[i][j], 0.f);

        for (int kc = 0; kc < 3; kc++){
            __syncthreads();
#pragma unroll
            for (int i = 0; i < 4; i++)
                *(uint4*)(bh + prow[i]*AHL + pc8[i]*8) = pf[i];
            ci++;
            if (ci < 12){
                int st = ci - 9;
                const __half* base = g_projh + (size_t)(st*64)*DIMC;
#pragma unroll
                for (int i = 0; i < 4; i++)
                    pf[i] = *(const uint4*)(base + (size_t)prow[i]*DIMC + pc8[i]*8);
            }
            __syncthreads();
#pragma unroll
            for (int ks = 0; ks < 4; ks++){
                FA fa0, fa1;
                wmma::load_matrix_sync(fa0, xh + (rt0  )*16*AHL + kc*64 + ks*16, AHL);
                wmma::load_matrix_sync(fa1, xh + (rt0+1)*16*AHL + kc*64 + ks*16, AHL);
                FB fb0, fb1;
                wmma::load_matrix_sync(fb0, bh + ks*16*AHL + cgi*16, AHL);
                wmma::load_matrix_sync(fb1, bh + ks*16*AHL + (cgi+6)*16, AHL);
                wmma::mma_sync(acc[0][0], fa0, fb0, acc[0][0]);
                wmma::mma_sync(acc[0][1], fa0, fb1, acc[0][1]);
                wmma::mma_sync(acc[1][0], fa1, fb0, acc[1][0]);
                wmma::mma_sync(acc[1][1], fa1, fb1, acc[1][1]);
            }
        }
#pragma unroll
        for (int i = 0; i < 2; i++){
            wmma::store_matrix_sync(FS + (rt0+i)*16*FLD + cgi*16,     acc[i][0], FLD, wmma::mem_row_major);
            wmma::store_matrix_sync(FS + (rt0+i)*16*FLD + (cgi+6)*16, acc[i][1], FLD, wmma::mem_row_major);
        }
        __syncthreads();

        // scatter (roll +3,+3) + proj bias
        float* ob = g_xattn + (size_t)b * NTOK * DIMC;
        for (int idx = t; idx < NTOKW*48; idx += AT_THREADS){
            int row = idx / 48, c4 = idx - row*48;
            int ti2 = row / WSZ, tj2 = row - ti2*WSZ;
            int sr = wr*WSZ + ti2 + SHIFT; if (sr >= HW) sr -= HW;
            int sc = wc*WSZ + tj2 + SHIFT; if (sc >= HW) sc -= HW;
            float4 v  = *(float4*)(FS + row*FLD + c4*4);
            float4 pb = *(const float4*)(proj_b + c4*4);
            v.x += pb.x; v.y += pb.y; v.z += pb.z; v.w += pb.w;
            *(float4*)(ob + (size_t)(sr*HW + sc)*DIMC + c4*4) = v;
        }
    }
}

// =====================================================================
// Kernel 2: fused MLP, fp16 wmma, 2 CTAs/SM, TM=64/256 threads,
// TH=64 (12 chunks) -> half the barrier crossings of R14.
// =====================================================================
#define ML_THREADS 256
#define TM 64
#define TH 64
#define XHL  200   // half stride, LN'd x
#define W1L  72    // half stride, w1 chunk [192][64]
#define HFL  68    // float stride, H accum scratch [64][64]
#define HHL  72    // half stride, gelu'd H [64][64]
#define W2L  200   // half stride, w2 chunk [64][192]
#define MO_XNH 0                      // half [64][200]  = 6400 floats
#define MO_W1H 6400                   // half [192][72]  = 6912 floats
#define MO_HF  13312                  // float [64][68]  = 4352
#define MO_HH  17664                  // half [64][72]   = 2304
#define MO_W2H 19968                  // half [64][200]  = 6400
#define MO_EPI 6400                   // float [64][196] (overlays W1H..W2H)
#define MLP_SMEM_FLOATS 26368
#define MLP_SMEM_BYTES  (MLP_SMEM_FLOATS*4)   // 105472 -> 2 CTAs/SM

__global__ __launch_bounds__(ML_THREADS, 2)
void mlp_kernel(const float* __restrict__ g2, const float* __restrict__ be2,
                const float* __restrict__ b1, const float* __restrict__ b2,
                float* __restrict__ out)
{
    extern __shared__ float sm[];
    __half* xnh = (__half*)(sm + MO_XNH);
    __half* w1h = (__half*)(sm + MO_W1H);
    float*  hf  = sm + MO_HF;
    __half* hhb = (__half*)(sm + MO_HH);
    __half* w2h = (__half*)(sm + MO_W2H);
    float*  epi = sm + MO_EPI;

    const int t = threadIdx.x;
    const int wid = t >> 5, lane = t & 31;
    const size_t tok0 = (size_t)blockIdx.x * TM;
    const float* xb = g_xattn + tok0 * DIMC;

    // load x into epi, LN -> half xnh
    for (int idx = t; idx < TM*48; idx += ML_THREADS){
        int r = idx / 48, c4 = idx - r*48;
        *(float4*)(epi + r*FLD + c4*4) = *(const float4*)(xb + (size_t)r*DIMC + c4*4);
    }
    __syncthreads();
    for (int r = wid; r < TM; r += 8){
        float s = 0.f, s2 = 0.f;
#pragma unroll
        for (int c = lane; c < DIMC; c += 32){
            float v = epi[r*FLD + c]; s += v; s2 += v*v;
        }
        s = warp_sum(s); s2 = warp_sum(s2);
        float mu = s * (1.0f/DIMC);
        float rs = rsqrtf(s2*(1.0f/DIMC) - mu*mu + 1e-5f);
#pragma unroll
        for (int c = lane; c < DIMC; c += 32){
            float v = (epi[r*FLD + c] - mu)*rs*g2[c] + be2[c];
            xnh[r*XHL + c] = __float2half_rn(v);
        }
    }

    const int r1 = wid & 3, c10 = (wid >> 2) * 2;  // GEMM1: 2 col tiles/warp
    const int rp = wid & 1, cp = wid >> 1;         // GEMM2: 2x3 tiles/warp

    FC acc2[2][3];
#pragma unroll
    for (int i = 0; i < 2; i++)
#pragma unroll
        for (int j = 0; j < 3; j++) wmma::fill_fragment(acc2[i][j], 0.f);

    for (int hc = 0; hc < 12; hc++){
        const int h0 = hc * TH;
        __syncthreads();   // prev chunk readers done (iter0: LN reads of epi done)

        // stage w1 [192][64] halfs (group 1): 1536 uint4, 6/thread
#pragma unroll
        for (int i = 0; i < 6; i++){
            int id = t + i*ML_THREADS;
            int row = id >> 3, c8 = id & 7;
            cp_async16(w1h + row*W1L + c8*8, g_w1h + (size_t)row*HIDDEN + h0 + c8*8);
        }
        cp_commit();
        // stage w2 [64][192] halfs (group 2): 1536 uint4, 6/thread
#pragma unroll
        for (int i = 0; i < 6; i++){
            int id = t + i*ML_THREADS;
            int row = id / 24, c8 = id - row*24;
            cp_async16(w2h + row*W2L + c8*8, g_w2h + (size_t)(h0 + row)*DIMC + c8*8);
        }
        cp_commit();

        cp_wait<1>();      // w1 arrived
        __syncthreads();

        // GEMM1: H[64,64] = Xn[64,192] @ W1c[192,64]; 2 tiles/warp, fa reuse
        FC a1[2];
        wmma::fill_fragment(a1[0], 0.f);
        wmma::fill_fragment(a1[1], 0.f);
#pragma unroll
        for (int ks = 0; ks < 12; ks++){
            FA fa; wmma::load_matrix_sync(fa, xnh + r1*16*XHL + ks*16, XHL);
            FB fb0, fb1;
            wmma::load_matrix_sync(fb0, w1h + ks*16*W1L + (c10  )*16, W1L);
            wmma::load_matrix_sync(fb1, w1h + ks*16*W1L + (c10+1)*16, W1L);
            wmma::mma_sync(a1[0], fa, fb0, a1[0]);
            wmma::mma_sync(a1[1], fa, fb1, a1[1]);
        }
#pragma unroll
        for (int j = 0; j < 2; j++)
            wmma::store_matrix_sync(hf + r1*16*HFL + (c10+j)*16, a1[j], HFL,
                                    wmma::mem_row_major);
        __syncwarp();
        {   // bias + exact GELU on own 2 tiles -> half
#pragma unroll
            for (int j = 0; j < 2; j++){
                float*  tf = hf  + r1*16*HFL + (c10+j)*16;
                __half* th = hhb + r1*16*HHL + (c10+j)*16;
                const float* bp = b1 + h0 + (c10+j)*16;
#pragma unroll
                for (int e = lane; e < 256; e += 32){
                    int rr = e >> 4, cc = e & 15;
                    th[rr*HHL + cc] = __float2half_rn(gelu_exact(tf[rr*HFL + cc] + bp[cc]));
                }
            }
        }
        cp_wait<0>();      // w2 arrived (hidden behind GEMM1 + GELU)
        __syncthreads();

        // GEMM2: acc2 += H[64,64] @ W2c[64,192]; K=64 -> 4 k-steps
#pragma unroll
        for (int ks = 0; ks < 4; ks++){
            FA fa0, fa1;
            wmma::load_matrix_sync(fa0, hhb + (2*rp  )*16*HHL + ks*16, HHL);
            wmma::load_matrix_sync(fa1, hhb + (2*rp+1)*16*HHL + ks*16, HHL);
#pragma unroll
            for (int j = 0; j < 3; j++){
                FB fb; wmma::load_matrix_sync(fb, w2h + ks*16*W2L + (3*cp + j)*16, W2L);
                wmma::mma_sync(acc2[0][j], fa0, fb, acc2[0][j]);
                wmma::mma_sync(acc2[1][j], fa1, fb, acc2[1][j]);
            }
        }
    }
    __syncthreads();

    // epilogue: acc2 -> epi (overlays weight buffers, all dead)
#pragma unroll
    for (int i = 0; i < 2; i++)
#pragma unroll
        for (int j = 0; j < 3; j++)
            wmma::store_matrix_sync(epi + (2*rp+i)*16*FLD + (3*cp+j)*16, acc2[i][j],
                                    FLD, wmma::mem_row_major);
    __syncthreads();

    float* ob = out + tok0 * DIMC;
    for (int idx = t; idx < TM*48; idx += ML_THREADS){
        int r = idx / 48, c4 = idx - r*48;
        float4 a  = *(float4*)(epi + r*FLD + c4*4);
        float4 xr = *(const float4*)(xb + (size_t)r*DIMC + c4*4);
        float4 bb = *(const float4*)(b2 + c4*4);
        a.x += xr.x + bb.x; a.y += xr.y + bb.y;
        a.z += xr.z + bb.z; a.w += xr.w + bb.w;
        *(float4*)(ob + (size_t)r*DIMC + c4*4) = a;
    }
}

// =====================================================================
// launch
// =====================================================================
extern "C" void kernel_launch(void* const* d_in, const int* in_sizes, int n_in,
                              void* d_out, int out_size)
{
    (void)in_sizes; (void)n_in; (void)out_size;
    const float* x      = (const float*)d_in[0];
    const float* qkv_w  = (const float*)d_in[1];
    const float* qkv_b  = (const float*)d_in[2];
    const float* proj_w = (const float*)d_in[3];
    const float* proj_b = (const float*)d_in[4];
    const float* g1     = (const float*)d_in[5];
    const float* be1    = (const float*)d_in[6];
    const float* g2     = (const float*)d_in[7];
    const float* be2    = (const float*)d_in[8];
    const float* w1     = (const float*)d_in[9];
    const float* b1     = (const float*)d_in[10];
    const float* w2     = (const float*)d_in[11];
    const float* b2     = (const float*)d_in[12];
    float* out = (float*)d_out;

    cudaFuncSetAttribute(attn_kernel, cudaFuncAttributeMaxDynamicSharedMemorySize, ATT_SMEM_BYTES);
    cudaFuncSetAttribute(mlp_kernel,  cudaFuncAttributeMaxDynamicSharedMemorySize, MLP_SMEM_BYTES);

    prep_kernel<<<RW_BLOCKS, RW_THREADS>>>(w1, w2, qkv_w, proj_w);
    attn_kernel<<<NBLKS, AT_THREADS, ATT_SMEM_BYTES>>>(x, qkv_b, proj_b, g1, be1);
    mlp_kernel<<<(BATCH*NTOK)/TM, ML_THREADS, MLP_SMEM_BYTES>>>(g2, be2, b1, b2, out);
}